// round 9
// baseline (speedup 1.0000x reference)
#include <cuda_runtime.h>
#include <cuda_bf16.h>
#include <cstdint>

// Problem constants
#define BB 4
#define SS 2048
#define CC 1024
#define EE 1024
#define HH 16
#define DD 64
#define BS (BB * SS)        // 8192
#define N_QKV (3 * EE)      // 3072

// f32 scratch
__device__ float g_q[BB * HH * SS * DD];   // [B,H,S,D], q pre-scaled by 1/8
__device__ float g_k[BB * HH * SS * DD];
__device__ float g_v[BB * HH * SS * DD];
__device__ float g_att[BS * EE];           // [B,S,E]

// bf16 split operands, pre-packed in mma-fragment order (see R7 layout notes).
__device__ __nv_bfloat16 g_ah[BS * CC],     g_al[BS * CC];
__device__ __nv_bfloat16 g_wqh[CC * N_QKV], g_wql[CC * N_QKV];
__device__ __nv_bfloat16 g_woh[CC * EE],    g_wol[CC * EE];

// ---------------------------------------------------------------------------
// Helpers
// ---------------------------------------------------------------------------
__device__ __forceinline__ uint32_t smem_u32(const void* p) {
    uint32_t a;
    asm("{ .reg .u64 t; cvta.to.shared.u64 t, %1; cvt.u32.u64 %0, t; }"
        : "=r"(a) : "l"(p));
    return a;
}
__device__ __forceinline__ void cp16(uint32_t s, const void* gp) {
    uint64_t g;
    asm("cvta.to.global.u64 %0, %1;" : "=l"(g) : "l"(gp));
    asm volatile("cp.async.cg.shared.global [%0], [%1], 16;" :: "r"(s), "l"(g) : "memory");
}
__device__ __forceinline__ void mma_bf16(float* d, const uint32_t* a,
                                         const uint32_t* b) {
    asm volatile(
        "mma.sync.aligned.m16n8k16.row.col.f32.bf16.bf16.f32 "
        "{%0,%1,%2,%3}, {%4,%5,%6,%7}, {%8,%9}, {%0,%1,%2,%3};"
        : "+f"(d[0]), "+f"(d[1]), "+f"(d[2]), "+f"(d[3])
        : "r"(a[0]), "r"(a[1]), "r"(a[2]), "r"(a[3]), "r"(b[0]), "r"(b[1]));
}
__device__ __forceinline__ unsigned f2tf(float x) {
    unsigned u;
    asm("cvt.rna.tf32.f32 %0, %1;" : "=r"(u) : "f"(x));
    return u;
}
__device__ __forceinline__ float f2tff(float x) {
    return __uint_as_float(f2tf(x));
}
__device__ __forceinline__ void mma_tf32(float* d, const unsigned* a, const unsigned* b) {
    asm volatile(
        "mma.sync.aligned.m16n8k8.row.col.f32.tf32.tf32.f32 "
        "{%0,%1,%2,%3}, {%4,%5,%6,%7}, {%8,%9}, {%0,%1,%2,%3};"
        : "+f"(d[0]), "+f"(d[1]), "+f"(d[2]), "+f"(d[3])
        : "r"(a[0]), "r"(a[1]), "r"(a[2]), "r"(a[3]), "r"(b[0]), "r"(b[1]));
}
__device__ __forceinline__ unsigned pack_bf16_hi(float x, float y) {
    __nv_bfloat16 h0 = __float2bfloat16(x);
    __nv_bfloat16 h1 = __float2bfloat16(y);
    return (unsigned)__bfloat16_as_ushort(h0) |
           ((unsigned)__bfloat16_as_ushort(h1) << 16);
}
__device__ __forceinline__ unsigned pack_bf16_lo(float x, float y) {
    float hx = __bfloat162float(__float2bfloat16(x));
    float hy = __bfloat162float(__float2bfloat16(y));
    __nv_bfloat16 l0 = __float2bfloat16(x - hx);
    __nv_bfloat16 l1 = __float2bfloat16(y - hy);
    return (unsigned)__bfloat16_as_ushort(l0) |
           ((unsigned)__bfloat16_as_ushort(l1) << 16);
}

// ---------------------------------------------------------------------------
// Prep kernels
// ---------------------------------------------------------------------------
template <int SRC>
__global__ __launch_bounds__(256) void prep_a(const float* __restrict__ xin)
{
    const float* src = (SRC == 1) ? g_att : xin;
    const int idx = blockIdx.x * 256 + threadIdx.x;
    const int m = idx >> 9;
    const int kp = idx & 511;
    const int k = kp * 2;
    float2 v = *(const float2*)(src + (size_t)m * CC + k);

    const int mt = m >> 7, mr = m & 127;
    const int kc = k >> 6, kl6 = k & 63;
    const int ks = kl6 >> 4, kl = kl6 & 15;
    const int mb = mr >> 4, r = mr & 15;
    const int lane = (r & 7) * 4 + ((kl & 7) >> 1);
    const int reg = (r >> 3) + 2 * (kl >> 3);
    const size_t byte = (size_t)(mt * 16 + kc) * 16384 +
                        (size_t)((ks * 8 + mb) * 32 + lane) * 16 + reg * 4;
    *(unsigned*)((char*)g_ah + byte) = pack_bf16_hi(v.x, v.y);
    *(unsigned*)((char*)g_al + byte) = pack_bf16_lo(v.x, v.y);
}

template <int MODE>
__global__ __launch_bounds__(256) void prep_b(const float* __restrict__ w)
{
    constexpr int N = (MODE == 0) ? N_QKV : EE;
    const int idx = blockIdx.x * 256 + threadIdx.x;
    const int kp = idx / N;
    const int n = idx - kp * N;
    const int k = kp * 2;
    const float w0 = w[(size_t)k * N + n];
    const float w1 = w[(size_t)(k + 1) * N + n];

    const int nt = n >> 7, nr = n & 127;
    const int kc = k >> 6, kl6 = k & 63;
    const int ks = kl6 >> 4, kl = kl6 & 15;
    const int nb = nr >> 3, gr = nr & 7;
    const int lane = gr * 4 + ((kl & 7) >> 1);
    const int reg = kl >> 3;
    const size_t byte = (size_t)(nt * 16 + kc) * 16384 +
                        (size_t)((ks * 16 + nb) * 32 + lane) * 8 + reg * 4;
    if (MODE == 0) {
        *(unsigned*)((char*)g_wqh + byte) = pack_bf16_hi(w0, w1);
        *(unsigned*)((char*)g_wql + byte) = pack_bf16_lo(w0, w1);
    } else {
        *(unsigned*)((char*)g_woh + byte) = pack_bf16_hi(w0, w1);
        *(unsigned*)((char*)g_wol + byte) = pack_bf16_lo(w0, w1);
    }
}

// ---------------------------------------------------------------------------
// Split-bf16 HMMA GEMM
// ---------------------------------------------------------------------------
#define GEMM_SMEM (2 * 65536)

template <int MODE>
__global__ __launch_bounds__(256, 1) void bf16_gemm(
    const float* __restrict__ bias, float* __restrict__ Cout)
{
    extern __shared__ __align__(128) char tsm[];
    const uint32_t sbase = smem_u32(tsm);

    const int t = threadIdx.x;
    const int lane = t & 31;
    const int warp = t >> 5;
    const int wm = warp & 1;
    const int wn = warp >> 1;
    const int lr = lane >> 2;
    const int lt = lane & 3;
    const int bx = blockIdx.x, by = blockIdx.y;

    const char* Ah = (const char*)g_ah;
    const char* Al = (const char*)g_al;
    const char* Bh = (MODE == 0) ? (const char*)g_wqh : (const char*)g_woh;
    const char* Bl = (MODE == 0) ? (const char*)g_wql : (const char*)g_wol;
    const size_t aoff = (size_t)by * 16 * 16384;
    const size_t boff = (size_t)bx * 16 * 16384;

    float acc[4][4][4];
#pragma unroll
    for (int mf = 0; mf < 4; mf++)
#pragma unroll
        for (int nf = 0; nf < 4; nf++)
#pragma unroll
            for (int r = 0; r < 4; r++) acc[mf][nf][r] = 0.0f;

    auto issue = [&](int c) {
        const uint32_t sdst = sbase + (c & 1) * 65536;
        const char* ga0 = Ah + aoff + (size_t)c * 16384;
        const char* ga1 = Al + aoff + (size_t)c * 16384;
        const char* gb0 = Bh + boff + (size_t)c * 16384;
        const char* gb1 = Bl + boff + (size_t)c * 16384;
#pragma unroll
        for (int i = 0; i < 4; i++) {
            const int o = (t + i * 256) * 16;
            cp16(sdst + o,         ga0 + o);
            cp16(sdst + 16384 + o, ga1 + o);
            cp16(sdst + 32768 + o, gb0 + o);
            cp16(sdst + 49152 + o, gb1 + o);
        }
        asm volatile("cp.async.commit_group;" ::: "memory");
    };

    issue(0);
    for (int c = 0; c < 16; ++c) {
        if (c + 1 < 16) {
            issue(c + 1);
            asm volatile("cp.async.wait_group 1;" ::: "memory");
        } else {
            asm volatile("cp.async.wait_group 0;" ::: "memory");
        }
        __syncthreads();

        const char* sa = tsm + (c & 1) * 65536;
#pragma unroll
        for (int ks = 0; ks < 4; ks++) {
            uint4 ah[4], al[4];
#pragma unroll
            for (int mf = 0; mf < 4; mf++) {
                const int off = ((ks * 8 + wm * 4 + mf) * 32 + lane) * 16;
                ah[mf] = *(const uint4*)(sa + off);
                al[mf] = *(const uint4*)(sa + 16384 + off);
            }
            uint2 bh[4], bl[4];
#pragma unroll
            for (int nf = 0; nf < 4; nf++) {
                const int off = ((ks * 16 + wn * 4 + nf) * 32 + lane) * 8;
                bh[nf] = *(const uint2*)(sa + 32768 + off);
                bl[nf] = *(const uint2*)(sa + 49152 + off);
            }
#pragma unroll
            for (int mf = 0; mf < 4; mf++)
#pragma unroll
                for (int nf = 0; nf < 4; nf++) {
                    mma_bf16(acc[mf][nf], &ah[mf].x, &bh[nf].x);
                    mma_bf16(acc[mf][nf], &al[mf].x, &bh[nf].x);
                    mma_bf16(acc[mf][nf], &ah[mf].x, &bl[nf].x);
                }
        }
        __syncthreads();
    }

    if (MODE == 0) {
        const int part = bx >> 3;
        float* dst = (part == 0) ? g_q : (part == 1) ? g_k : g_v;
        const float mult = (part == 0) ? 0.125f : 1.0f;
#pragma unroll
        for (int nf = 0; nf < 4; nf++) {
            const int col = bx * 128 + wn * 32 + nf * 8 + 2 * lt;
            const float bi0 = bias[col], bi1 = bias[col + 1];
            const int e = col & 1023;
            const int h = e >> 6, d = e & 63;
#pragma unroll
            for (int mf = 0; mf < 4; mf++) {
#pragma unroll
                for (int half = 0; half < 2; half++) {
                    const int row = by * 128 + wm * 64 + mf * 16 + lr + half * 8;
                    const int b = row >> 11, s = row & 2047;
                    float2 v;
                    v.x = (acc[mf][nf][half * 2 + 0] + bi0) * mult;
                    v.y = (acc[mf][nf][half * 2 + 1] + bi1) * mult;
                    *(float2*)&dst[(((size_t)(b * HH + h)) * SS + s) * DD + d] = v;
                }
            }
        }
    } else {
#pragma unroll
        for (int nf = 0; nf < 4; nf++) {
            const int col = bx * 128 + wn * 32 + nf * 8 + 2 * lt;
            const float bi0 = bias[col], bi1 = bias[col + 1];
#pragma unroll
            for (int mf = 0; mf < 4; mf++) {
#pragma unroll
                for (int half = 0; half < 2; half++) {
                    const int row = by * 128 + wm * 64 + mf * 16 + lr + half * 8;
                    float2 v;
                    v.x = acc[mf][nf][half * 2 + 0] + bi0;
                    v.y = acc[mf][nf][half * 2 + 1] + bi1;
                    *(float2*)&Cout[(size_t)row * EE + col] = v;
                }
            }
        }
    }
}

// ---------------------------------------------------------------------------
// Flash attention, tf32 HMMA with fragment-packed smem.
// smem: Qf 32KB [ks8][mb8][lane32]u4 | Pf 40KB (8 warps x 5120B, slot stride
// 160B for conflict-free LDS.128) | Kf 16KB [ks8][nf8][lane32]u2 | Vf 16KB.
// ---------------------------------------------------------------------------
#define FA_SMEM 106496

__global__ __launch_bounds__(256, 2) void fa_tf32()
{
    extern __shared__ __align__(16) char fsm[];
    float* Qf = (float*)fsm;                  // 32768 B
    char*  Pf = fsm + 32768;                  // 40960 B
    float* Kf = (float*)(fsm + 73728);        // 16384 B
    float* Vf = (float*)(fsm + 90112);        // 16384 B

    const int qt = blockIdx.x;                // 0..15
    const int bh = blockIdx.y;                // 0..63
    const int t = threadIdx.x;
    const int lane = t & 31, warp = t >> 5;
    const int lr = lane >> 2, lt = lane & 3;

    const float* qbase = g_q + ((size_t)bh * SS + qt * 128) * DD;
    const float* kbase = g_k + (size_t)bh * SS * DD;
    const float* vbase = g_v + (size_t)bh * SS * DD;

    // ---- stage Q [128][64] as tf32 A-fragments (once)
    {
        const int row = t & 127;
        const int mb = row >> 4;
        const int rr = row & 15;
        const int lrq = rr & 7, rh = rr >> 3;
        const int cq = (t >> 7) * 32;
#pragma unroll
        for (int i = 0; i < 8; i++) {
            const int cb = cq + i * 4;
            float4 v = *(const float4*)(qbase + row * DD + cb);
            const int ks = cb >> 3;
            const int ch = (cb & 7) >> 2;
            float vv[4] = {v.x, v.y, v.z, v.w};
#pragma unroll
            for (int j = 0; j < 4; j++)
                Qf[((ks * 8 + mb) * 32 + lrq * 4 + j) * 4 + rh + 2 * ch] =
                    f2tff(vv[j]);
        }
    }

    float m0 = -1e30f, m1 = -1e30f, l0 = 0.0f, l1 = 0.0f;
    float o[8][4];
#pragma unroll
    for (int nf = 0; nf < 8; nf++)
#pragma unroll
        for (int r = 0; r < 4; r++) o[nf][r] = 0.0f;

    char* Pfw = Pf + warp * 5120;
    const int ps0 = (lt < 2) ? 2 * lt : 2 * lt - 4;
    const int pwo = (lt < 2) ? 0 : 8;         // byte offset of word pair

    for (int kt = 0; kt < SS / 64; kt++) {
        __syncthreads();   // previous tile's reads done before restaging
        // ---- stage K,V [64][64] as tf32 B-fragments
        {
            const int row = t & 63;
            const int cq = (t >> 6) * 16;
            const float* kb = kbase + (size_t)(kt * 64 + row) * DD;
            const float* vb = vbase + (size_t)(kt * 64 + row) * DD;
            const int nfk = row >> 3, lrk = row & 7;   // K: nf/lr from row
            const int ksv = row >> 3, ltv = row & 7;   // V: ks/lt from row
#pragma unroll
            for (int i = 0; i < 4; i++) {
                const int cb = cq + i * 4;
                const int ks = cb >> 3;
                const int rg = (cb & 7) >> 2;
                float4 kx = *(const float4*)(kb + cb);
                float4 vx = *(const float4*)(vb + cb);
                float kk4[4] = {kx.x, kx.y, kx.z, kx.w};
                float vv4[4] = {vx.x, vx.y, vx.z, vx.w};
#pragma unroll
                for (int j = 0; j < 4; j++) {
                    Kf[((ks * 8 + nfk) * 32 + lrk * 4 + j) * 2 + rg] =
                        f2tff(kk4[j]);
                    const int lrv = (cb & 7) + j;
                    Vf[((ksv * 8 + ks) * 32 + lrv * 4 + (ltv & 3)) * 2 +
                       (ltv >> 2)] = f2tff(vv4[j]);
                }
            }
        }
        __syncthreads();

        // ---- S = Q K^T (m16 x n64, k=64)
        float s[8][4];
#pragma unroll
        for (int nf = 0; nf < 8; nf++)
#pragma unroll
            for (int r = 0; r < 4; r++) s[nf][r] = 0.0f;

#pragma unroll
        for (int ks = 0; ks < 8; ks++) {
            uint4 qa = *(const uint4*)&Qf[((ks * 8 + warp) * 32 + lane) * 4];
#pragma unroll
            for (int nf = 0; nf < 8; nf++) {
                uint2 kb2 = *(const uint2*)&Kf[((ks * 8 + nf) * 32 + lane) * 2];
                mma_tf32(s[nf], (const unsigned*)&qa, (const unsigned*)&kb2);
            }
        }

        // ---- online softmax; write P as A-fragments into Pf
        float rm0 = -1e30f, rm1 = -1e30f;
#pragma unroll
        for (int nf = 0; nf < 8; nf++) {
            rm0 = fmaxf(rm0, fmaxf(s[nf][0], s[nf][1]));
            rm1 = fmaxf(rm1, fmaxf(s[nf][2], s[nf][3]));
        }
        rm0 = fmaxf(rm0, __shfl_xor_sync(0xffffffffu, rm0, 1));
        rm0 = fmaxf(rm0, __shfl_xor_sync(0xffffffffu, rm0, 2));
        rm1 = fmaxf(rm1, __shfl_xor_sync(0xffffffffu, rm1, 1));
        rm1 = fmaxf(rm1, __shfl_xor_sync(0xffffffffu, rm1, 2));
        const float nm0 = fmaxf(m0, rm0), nm1 = fmaxf(m1, rm1);
        float rs0 = 0.0f, rs1 = 0.0f;
#pragma unroll
        for (int nf = 0; nf < 8; nf++) {
            float p0 = __expf(s[nf][0] - nm0);
            float p1 = __expf(s[nf][1] - nm0);
            float p2 = __expf(s[nf][2] - nm1);
            float p3 = __expf(s[nf][3] - nm1);
            rs0 += p0 + p1;
            rs1 += p2 + p3;
            // word pair (row lr, row lr+8) for cols 2lt / 2lt+1
            float2 wa = {f2tff(p0), f2tff(p2)};
            float2 wb = {f2tff(p1), f2tff(p3)};
            char* base = Pfw + nf * 640 + lr * 16 + pwo;
            *(float2*)(base + ps0 * 160) = wa;
            *(float2*)(base + (ps0 + 1) * 160) = wb;
        }
        rs0 += __shfl_xor_sync(0xffffffffu, rs0, 1);
        rs0 += __shfl_xor_sync(0xffffffffu, rs0, 2);
        rs1 += __shfl_xor_sync(0xffffffffu, rs1, 1);
        rs1 += __shfl_xor_sync(0xffffffffu, rs1, 2);
        const float al0 = __expf(m0 - nm0), al1 = __expf(m1 - nm1);
        l0 = l0 * al0 + rs0;
        l1 = l1 * al1 + rs1;
        m0 = nm0; m1 = nm1;
#pragma unroll
        for (int nf = 0; nf < 8; nf++) {
            o[nf][0] *= al0; o[nf][1] *= al0;
            o[nf][2] *= al1; o[nf][3] *= al1;
        }
        __syncwarp();

        // ---- O += P V (m16 x n64(d), k=64(seq))
#pragma unroll
        for (int ks = 0; ks < 8; ks++) {
            uint4 pa = *(const uint4*)(Pfw + ks * 640 + lt * 160 + lr * 16);
#pragma unroll
            for (int nf = 0; nf < 8; nf++) {
                uint2 vb2 = *(const uint2*)&Vf[((ks * 8 + nf) * 32 + lane) * 2];
                mma_tf32(o[nf], (const unsigned*)&pa, (const unsigned*)&vb2);
            }
        }
    }

    // ---- epilogue: normalize and scatter to g_att [B,S,E]
    const int b = bh >> 4, h = bh & 15;
    const float inv0 = 1.0f / l0, inv1 = 1.0f / l1;
    const int srow0 = qt * 128 + warp * 16 + lr;
    float* base0 = g_att + ((size_t)b * SS + srow0) * EE + h * DD;
    float* base1 = base0 + (size_t)8 * EE;
#pragma unroll
    for (int nf = 0; nf < 8; nf++) {
        float2 v0 = {o[nf][0] * inv0, o[nf][1] * inv0};
        float2 v1 = {o[nf][2] * inv1, o[nf][3] * inv1};
        *(float2*)(base0 + nf * 8 + 2 * lt) = v0;
        *(float2*)(base1 + nf * 8 + 2 * lt) = v1;
    }
}

// ---------------------------------------------------------------------------
extern "C" void kernel_launch(void* const* d_in, const int* in_sizes, int n_in,
                              void* d_out, int out_size)
{
    const float* x     = (const float*)d_in[0];
    const float* w_qkv = (const float*)d_in[1];
    const float* b_qkv = (const float*)d_in[2];
    const float* w_out = (const float*)d_in[3];
    const float* b_out = (const float*)d_in[4];
    float* out = (float*)d_out;

    (void)in_sizes; (void)n_in; (void)out_size;

    cudaFuncSetAttribute(bf16_gemm<0>,
                         cudaFuncAttributeMaxDynamicSharedMemorySize, GEMM_SMEM);
    cudaFuncSetAttribute(bf16_gemm<1>,
                         cudaFuncAttributeMaxDynamicSharedMemorySize, GEMM_SMEM);
    cudaFuncSetAttribute(fa_tf32,
                         cudaFuncAttributeMaxDynamicSharedMemorySize, FA_SMEM);

    // 1) split + fragment-pack x and w_qkv
    prep_a<0><<<BS * 512 / 256, 256>>>(x);
    prep_b<0><<<512 * N_QKV / 256, 256>>>(w_qkv);
    // 2) QKV projection (split-bf16 HMMA)
    {
        dim3 grid(N_QKV / 128, BS / 128);
        bf16_gemm<0><<<grid, 256, GEMM_SMEM>>>(b_qkv, nullptr);
    }
    // 3) attention (tf32 HMMA, fragment-packed smem)
    {
        dim3 grid(SS / 128, BB * HH);
        fa_tf32<<<grid, 256, FA_SMEM>>>();
    }
    // 4) split + fragment-pack att output and w_out
    prep_a<1><<<BS * 512 / 256, 256>>>(nullptr);
    prep_b<1><<<512 * EE / 256, 256>>>(w_out);
    // 5) output projection (split-bf16 HMMA)
    {
        dim3 grid(EE / 128, BS / 128);
        bf16_gemm<1><<<grid, 256, GEMM_SMEM>>>(b_out, out);
    }
}

// round 11
// speedup vs baseline: 1.6950x; 1.6950x over previous
#include <cuda_runtime.h>
#include <cuda_bf16.h>
#include <cuda_fp16.h>
#include <cstdint>

// Problem constants
#define BB 4
#define SS 2048
#define CC 1024
#define EE 1024
#define HH 16
#define DD 64
#define BS (BB * SS)        // 8192
#define N_QKV (3 * EE)      // 3072

// f32 scratch
__device__ float g_att[BS * EE];           // [B,S,E]

// Fragment-packed attention operands (written by QKV GEMM epilogue):
// Q: per (bh, qt128): 8192 words [ks8][mb8][lane32][4regs]  (tf32, pre-scaled)
// K: per (bh, kt64):  4096 words [ks8][nf8][lane32][2regs]  (tf32)
// V: per (bh, kt64):  4096 f16x2 words -> 8192 halves [ksp4][nf8][lane32][2regs x f16x2]
__device__ float  g_qf[BB * HH * 16 * 8192];
__device__ float  g_kf[BB * HH * 32 * 4096];
__device__ __half g_vf[BB * HH * 32 * 8192];

// bf16 split GEMM operands, mma-fragment order (R7 layout, validated)
__device__ __nv_bfloat16 g_ah[BS * CC],     g_al[BS * CC];
__device__ __nv_bfloat16 g_wqh[CC * N_QKV], g_wql[CC * N_QKV];
__device__ __nv_bfloat16 g_woh[CC * EE],    g_wol[CC * EE];

// ---------------------------------------------------------------------------
// Helpers
// ---------------------------------------------------------------------------
__device__ __forceinline__ uint32_t smem_u32(const void* p) {
    uint32_t a;
    asm("{ .reg .u64 t; cvta.to.shared.u64 t, %1; cvt.u32.u64 %0, t; }"
        : "=r"(a) : "l"(p));
    return a;
}
__device__ __forceinline__ void cp16(uint32_t s, const void* gp) {
    uint64_t g;
    asm("cvta.to.global.u64 %0, %1;" : "=l"(g) : "l"(gp));
    asm volatile("cp.async.cg.shared.global [%0], [%1], 16;" :: "r"(s), "l"(g) : "memory");
}
__device__ __forceinline__ void mma_bf16(float* d, const uint32_t* a,
                                         const uint32_t* b) {
    asm volatile(
        "mma.sync.aligned.m16n8k16.row.col.f32.bf16.bf16.f32 "
        "{%0,%1,%2,%3}, {%4,%5,%6,%7}, {%8,%9}, {%0,%1,%2,%3};"
        : "+f"(d[0]), "+f"(d[1]), "+f"(d[2]), "+f"(d[3])
        : "r"(a[0]), "r"(a[1]), "r"(a[2]), "r"(a[3]), "r"(b[0]), "r"(b[1]));
}
__device__ __forceinline__ void mma_f16(float* d, const uint32_t* a,
                                        const uint32_t* b) {
    asm volatile(
        "mma.sync.aligned.m16n8k16.row.col.f32.f16.f16.f32 "
        "{%0,%1,%2,%3}, {%4,%5,%6,%7}, {%8,%9}, {%0,%1,%2,%3};"
        : "+f"(d[0]), "+f"(d[1]), "+f"(d[2]), "+f"(d[3])
        : "r"(a[0]), "r"(a[1]), "r"(a[2]), "r"(a[3]), "r"(b[0]), "r"(b[1]));
}
__device__ __forceinline__ unsigned f2tf(float x) {
    unsigned u;
    asm("cvt.rna.tf32.f32 %0, %1;" : "=r"(u) : "f"(x));
    return u;
}
__device__ __forceinline__ float f2tff(float x) {
    return __uint_as_float(f2tf(x));
}
__device__ __forceinline__ void mma_tf32(float* d, const unsigned* a, const unsigned* b) {
    asm volatile(
        "mma.sync.aligned.m16n8k8.row.col.f32.tf32.tf32.f32 "
        "{%0,%1,%2,%3}, {%4,%5,%6,%7}, {%8,%9}, {%0,%1,%2,%3};"
        : "+f"(d[0]), "+f"(d[1]), "+f"(d[2]), "+f"(d[3])
        : "r"(a[0]), "r"(a[1]), "r"(a[2]), "r"(a[3]), "r"(b[0]), "r"(b[1]));
}
// pack (lo, hi) -> f16x2 word  (d.lo = lo, d.hi = hi)
__device__ __forceinline__ uint32_t pack_f16x2(float lo, float hi) {
    uint32_t r;
    asm("cvt.rn.f16x2.f32 %0, %1, %2;" : "=r"(r) : "f"(hi), "f"(lo));
    return r;
}
__device__ __forceinline__ unsigned pack_bf16_hi(float x, float y) {
    __nv_bfloat16 h0 = __float2bfloat16(x);
    __nv_bfloat16 h1 = __float2bfloat16(y);
    return (unsigned)__bfloat16_as_ushort(h0) |
           ((unsigned)__bfloat16_as_ushort(h1) << 16);
}
__device__ __forceinline__ unsigned pack_bf16_lo(float x, float y) {
    float hx = __bfloat162float(__float2bfloat16(x));
    float hy = __bfloat162float(__float2bfloat16(y));
    __nv_bfloat16 l0 = __float2bfloat16(x - hx);
    __nv_bfloat16 l1 = __float2bfloat16(y - hy);
    return (unsigned)__bfloat16_as_ushort(l0) |
           ((unsigned)__bfloat16_as_ushort(l1) << 16);
}

// ---------------------------------------------------------------------------
// Prep kernels (unchanged, validated)
// ---------------------------------------------------------------------------
template <int SRC>
__global__ __launch_bounds__(256) void prep_a(const float* __restrict__ xin)
{
    const float* src = (SRC == 1) ? g_att : xin;
    const int idx = blockIdx.x * 256 + threadIdx.x;
    const int m = idx >> 9;
    const int kp = idx & 511;
    const int k = kp * 2;
    float2 v = *(const float2*)(src + (size_t)m * CC + k);

    const int mt = m >> 7, mr = m & 127;
    const int kc = k >> 6, kl6 = k & 63;
    const int ks = kl6 >> 4, kl = kl6 & 15;
    const int mb = mr >> 4, r = mr & 15;
    const int lane = (r & 7) * 4 + ((kl & 7) >> 1);
    const int reg = (r >> 3) + 2 * (kl >> 3);
    const size_t byte = (size_t)(mt * 16 + kc) * 16384 +
                        (size_t)((ks * 8 + mb) * 32 + lane) * 16 + reg * 4;
    *(unsigned*)((char*)g_ah + byte) = pack_bf16_hi(v.x, v.y);
    *(unsigned*)((char*)g_al + byte) = pack_bf16_lo(v.x, v.y);
}

template <int MODE>
__global__ __launch_bounds__(256) void prep_b(const float* __restrict__ w)
{
    constexpr int N = (MODE == 0) ? N_QKV : EE;
    const int idx = blockIdx.x * 256 + threadIdx.x;
    const int kp = idx / N;
    const int n = idx - kp * N;
    const int k = kp * 2;
    const float w0 = w[(size_t)k * N + n];
    const float w1 = w[(size_t)(k + 1) * N + n];

    const int nt = n >> 7, nr = n & 127;
    const int kc = k >> 6, kl6 = k & 63;
    const int ks = kl6 >> 4, kl = kl6 & 15;
    const int nb = nr >> 3, gr = nr & 7;
    const int lane = gr * 4 + ((kl & 7) >> 1);
    const int reg = kl >> 3;
    const size_t byte = (size_t)(nt * 16 + kc) * 16384 +
                        (size_t)((ks * 16 + nb) * 32 + lane) * 8 + reg * 4;
    if (MODE == 0) {
        *(unsigned*)((char*)g_wqh + byte) = pack_bf16_hi(w0, w1);
        *(unsigned*)((char*)g_wql + byte) = pack_bf16_lo(w0, w1);
    } else {
        *(unsigned*)((char*)g_woh + byte) = pack_bf16_hi(w0, w1);
        *(unsigned*)((char*)g_wol + byte) = pack_bf16_lo(w0, w1);
    }
}

// ---------------------------------------------------------------------------
// Split-bf16 HMMA GEMM. MODE 0 epilogue now writes Q/K/V directly in
// attention mma-fragment order (tf32 Q/K, fp16 V). MODE 1 unchanged.
// ---------------------------------------------------------------------------
#define GEMM_SMEM (2 * 65536)

template <int MODE>
__global__ __launch_bounds__(256, 1) void bf16_gemm(
    const float* __restrict__ bias, float* __restrict__ Cout)
{
    extern __shared__ __align__(128) char tsm[];
    const uint32_t sbase = smem_u32(tsm);

    const int t = threadIdx.x;
    const int lane = t & 31;
    const int warp = t >> 5;
    const int wm = warp & 1;
    const int wn = warp >> 1;
    const int lr = lane >> 2;
    const int lt = lane & 3;
    const int bx = blockIdx.x, by = blockIdx.y;

    const char* Ah = (const char*)g_ah;
    const char* Al = (const char*)g_al;
    const char* Bh = (MODE == 0) ? (const char*)g_wqh : (const char*)g_woh;
    const char* Bl = (MODE == 0) ? (const char*)g_wql : (const char*)g_wol;
    const size_t aoff = (size_t)by * 16 * 16384;
    const size_t boff = (size_t)bx * 16 * 16384;

    float acc[4][4][4];
#pragma unroll
    for (int mf = 0; mf < 4; mf++)
#pragma unroll
        for (int nf = 0; nf < 4; nf++)
#pragma unroll
            for (int r = 0; r < 4; r++) acc[mf][nf][r] = 0.0f;

    auto issue = [&](int c) {
        const uint32_t sdst = sbase + (c & 1) * 65536;
        const char* ga0 = Ah + aoff + (size_t)c * 16384;
        const char* ga1 = Al + aoff + (size_t)c * 16384;
        const char* gb0 = Bh + boff + (size_t)c * 16384;
        const char* gb1 = Bl + boff + (size_t)c * 16384;
#pragma unroll
        for (int i = 0; i < 4; i++) {
            const int o = (t + i * 256) * 16;
            cp16(sdst + o,         ga0 + o);
            cp16(sdst + 16384 + o, ga1 + o);
            cp16(sdst + 32768 + o, gb0 + o);
            cp16(sdst + 49152 + o, gb1 + o);
        }
        asm volatile("cp.async.commit_group;" ::: "memory");
    };

    issue(0);
    for (int c = 0; c < 16; ++c) {
        if (c + 1 < 16) {
            issue(c + 1);
            asm volatile("cp.async.wait_group 1;" ::: "memory");
        } else {
            asm volatile("cp.async.wait_group 0;" ::: "memory");
        }
        __syncthreads();

        const char* sa = tsm + (c & 1) * 65536;
#pragma unroll
        for (int ks = 0; ks < 4; ks++) {
            uint4 ah[4], al[4];
#pragma unroll
            for (int mf = 0; mf < 4; mf++) {
                const int off = ((ks * 8 + wm * 4 + mf) * 32 + lane) * 16;
                ah[mf] = *(const uint4*)(sa + off);
                al[mf] = *(const uint4*)(sa + 16384 + off);
            }
            uint2 bh[4], bl[4];
#pragma unroll
            for (int nf = 0; nf < 4; nf++) {
                const int off = ((ks * 16 + wn * 4 + nf) * 32 + lane) * 8;
                bh[nf] = *(const uint2*)(sa + 32768 + off);
                bl[nf] = *(const uint2*)(sa + 49152 + off);
            }
#pragma unroll
            for (int mf = 0; mf < 4; mf++)
#pragma unroll
                for (int nf = 0; nf < 4; nf++) {
                    mma_bf16(acc[mf][nf], &ah[mf].x, &bh[nf].x);
                    mma_bf16(acc[mf][nf], &al[mf].x, &bh[nf].x);
                    mma_bf16(acc[mf][nf], &ah[mf].x, &bl[nf].x);
                }
        }
        __syncthreads();
    }

    if (MODE == 0) {
        const int part = bx >> 3;
#pragma unroll
        for (int nf = 0; nf < 4; nf++) {
            const int col = bx * 128 + wn * 32 + nf * 8 + 2 * lt;
            const float bi0 = bias[col], bi1 = bias[col + 1];
            const int e = col & 1023;
            const int h = e >> 6, d0 = e & 63;
#pragma unroll
            for (int mf = 0; mf < 4; mf++) {
#pragma unroll
                for (int half = 0; half < 2; half++) {
                    const int row = by * 128 + wm * 64 + mf * 16 + lr + half * 8;
                    const int b = row >> 11, s = row & 2047;
                    float v0 = acc[mf][nf][half * 2 + 0] + bi0;
                    float v1 = acc[mf][nf][half * 2 + 1] + bi1;
                    if (part == 0) {
                        // Q fragment store (tf32, x0.125)
                        const int qt = s >> 7, r128 = s & 127;
                        const int mb = r128 >> 4, rr = r128 & 15;
                        float* base = g_qf +
                            ((size_t)(b * HH + h) * 16 + qt) * 8192;
#pragma unroll
                        for (int c2 = 0; c2 < 2; c2++) {
                            const int d = d0 + c2;
                            const float val = (c2 ? v1 : v0) * 0.125f;
                            const int idx =
                                (((d >> 3) * 8 + mb) * 32 +
                                 (rr & 7) * 4 + (d & 3)) * 4 +
                                (rr >> 3) + 2 * ((d & 7) >> 2);
                            base[idx] = f2tff(val);
                        }
                    } else if (part == 1) {
                        // K fragment store (tf32)
                        const int kt = s >> 6, seq = s & 63;
                        float* base = g_kf +
                            ((size_t)(b * HH + h) * 32 + kt) * 4096;
#pragma unroll
                        for (int c2 = 0; c2 < 2; c2++) {
                            const int d = d0 + c2;
                            const float val = c2 ? v1 : v0;
                            const int idx =
                                (((d >> 3) * 8 + (seq >> 3)) * 32 +
                                 (seq & 7) * 4 + (d & 3)) * 2 +
                                ((d & 7) >> 2);
                            base[idx] = f2tff(val);
                        }
                    } else {
                        // V fragment store (fp16)
                        const int kt = s >> 6, seq = s & 63;
                        const int ksp = seq >> 4, kl = seq & 15;
                        __half* base = g_vf +
                            ((size_t)(b * HH + h) * 32 + kt) * 8192;
#pragma unroll
                        for (int c2 = 0; c2 < 2; c2++) {
                            const int d = d0 + c2;
                            const float val = c2 ? v1 : v0;
                            const int idx =
                                ((((ksp * 8 + (d >> 3)) * 32 +
                                   (d & 7) * 4 + ((kl & 7) >> 1)) * 2 +
                                  (kl >> 3)) << 1) + (kl & 1);
                            base[idx] = __float2half_rn(val);
                        }
                    }
                }
            }
        }
    } else {
#pragma unroll
        for (int nf = 0; nf < 4; nf++) {
            const int col = bx * 128 + wn * 32 + nf * 8 + 2 * lt;
            const float bi0 = bias[col], bi1 = bias[col + 1];
#pragma unroll
            for (int mf = 0; mf < 4; mf++) {
#pragma unroll
                for (int half = 0; half < 2; half++) {
                    const int row = by * 128 + wm * 64 + mf * 16 + lr + half * 8;
                    float2 v;
                    v.x = acc[mf][nf][half * 2 + 0] + bi0;
                    v.y = acc[mf][nf][half * 2 + 1] + bi1;
                    *(float2*)&Cout[(size_t)row * EE + col] = v;
                }
            }
        }
    }
}

// ---------------------------------------------------------------------------
// Flash attention. QK: tf32 m16n8k8 from pre-packed fragments (cp.async in).
// PV: fp16 m16n8k16, P packed register-only from the S C-fragment (FA2 trick).
// smem: Q 32KB | 2 stages x (K 16KB + V 8KB) = 80KB total. No in-loop STS.
// ---------------------------------------------------------------------------
#define FA_SMEM (32768 + 2 * 24576)   // 81920

__global__ __launch_bounds__(256, 2) void fa_tf32()
{
    extern __shared__ __align__(16) char fsm[];
    const uint32_t sb = smem_u32(fsm);

    const int qt = blockIdx.x;                // 0..15
    const int bh = blockIdx.y;                // 0..63
    const int t = threadIdx.x;
    const int lane = t & 31, warp = t >> 5;
    const int lr = lane >> 2, lt = lane & 3;

    const char* gq = (const char*)(g_qf + ((size_t)bh * 16 + qt) * 8192);
    const char* gk = (const char*)(g_kf + (size_t)bh * 32 * 4096);
    const char* gv = (const char*)(g_vf + (size_t)bh * 32 * 8192);

    // prologue: Q tile (32KB) as its own group
#pragma unroll
    for (int i = 0; i < 8; i++)
        cp16(sb + i * 4096 + t * 16, gq + i * 4096 + t * 16);
    asm volatile("cp.async.commit_group;" ::: "memory");

    auto issue = [&](int kt) {
        const uint32_t sd = sb + 32768 + (kt & 1) * 24576;
        const char* kp = gk + (size_t)kt * 16384;
        const char* vp = gv + (size_t)kt * 16384;   // 8192 halves = 16384 B
#pragma unroll
        for (int i = 0; i < 4; i++)
            cp16(sd + i * 4096 + t * 16, kp + i * 4096 + t * 16);
#pragma unroll
        for (int i = 0; i < 2; i++)
            cp16(sd + 16384 + i * 4096 + t * 16, vp + i * 4096 + t * 16);
        asm volatile("cp.async.commit_group;" ::: "memory");
    };
    issue(0);

    float m0 = -1e30f, m1 = -1e30f, l0 = 0.0f, l1 = 0.0f;
    float o[8][4];
#pragma unroll
    for (int nf = 0; nf < 8; nf++)
#pragma unroll
        for (int r = 0; r < 4; r++) o[nf][r] = 0.0f;

    const float* Qw = (const float*)fsm;

    for (int kt = 0; kt < SS / 64; kt++) {
        if (kt + 1 < SS / 64) {
            issue(kt + 1);
            asm volatile("cp.async.wait_group 1;" ::: "memory");
        } else {
            asm volatile("cp.async.wait_group 0;" ::: "memory");
        }
        __syncthreads();

        const char* st = fsm + 32768 + (kt & 1) * 24576;
        const float* Kw = (const float*)st;
        const uint2* Vw = (const uint2*)(st + 16384);

        // ---- S = Q K^T (tf32 m16n8k8; m16 x n64, k=64)
        float s[8][4];
#pragma unroll
        for (int nf = 0; nf < 8; nf++)
#pragma unroll
            for (int r = 0; r < 4; r++) s[nf][r] = 0.0f;

#pragma unroll
        for (int ks = 0; ks < 8; ks++) {
            uint4 qa = *(const uint4*)(Qw + ((ks * 8 + warp) * 32 + lane) * 4);
#pragma unroll
            for (int nf = 0; nf < 8; nf++) {
                uint2 kb = *(const uint2*)(Kw + ((ks * 8 + nf) * 32 + lane) * 2);
                mma_tf32(s[nf], (const unsigned*)&qa, (const unsigned*)&kb);
            }
        }

        // ---- online softmax (rows lr, lr+8); p kept in s[][]
        float rm0 = -1e30f, rm1 = -1e30f;
#pragma unroll
        for (int nf = 0; nf < 8; nf++) {
            rm0 = fmaxf(rm0, fmaxf(s[nf][0], s[nf][1]));
            rm1 = fmaxf(rm1, fmaxf(s[nf][2], s[nf][3]));
        }
        rm0 = fmaxf(rm0, __shfl_xor_sync(0xffffffffu, rm0, 1));
        rm0 = fmaxf(rm0, __shfl_xor_sync(0xffffffffu, rm0, 2));
        rm1 = fmaxf(rm1, __shfl_xor_sync(0xffffffffu, rm1, 1));
        rm1 = fmaxf(rm1, __shfl_xor_sync(0xffffffffu, rm1, 2));
        const float nm0 = fmaxf(m0, rm0), nm1 = fmaxf(m1, rm1);
        float rs0 = 0.0f, rs1 = 0.0f;
#pragma unroll
        for (int nf = 0; nf < 8; nf++) {
            float p0 = __expf(s[nf][0] - nm0);
            float p1 = __expf(s[nf][1] - nm0);
            float p2 = __expf(s[nf][2] - nm1);
            float p3 = __expf(s[nf][3] - nm1);
            rs0 += p0 + p1;
            rs1 += p2 + p3;
            s[nf][0] = p0; s[nf][1] = p1; s[nf][2] = p2; s[nf][3] = p3;
        }
        rs0 += __shfl_xor_sync(0xffffffffu, rs0, 1);
        rs0 += __shfl_xor_sync(0xffffffffu, rs0, 2);
        rs1 += __shfl_xor_sync(0xffffffffu, rs1, 1);
        rs1 += __shfl_xor_sync(0xffffffffu, rs1, 2);
        const float al0 = __expf(m0 - nm0), al1 = __expf(m1 - nm1);
        l0 = l0 * al0 + rs0;
        l1 = l1 * al1 + rs1;
        m0 = nm0; m1 = nm1;
#pragma unroll
        for (int nf = 0; nf < 8; nf++) {
            o[nf][0] *= al0; o[nf][1] *= al0;
            o[nf][2] *= al1; o[nf][3] *= al1;
        }

        // ---- O += P V (fp16 m16n8k16; P packed from S C-frag, register-only)
#pragma unroll
        for (int ksp = 0; ksp < 4; ksp++) {
            uint32_t pa[4];
            pa[0] = pack_f16x2(s[2 * ksp][0],     s[2 * ksp][1]);
            pa[1] = pack_f16x2(s[2 * ksp][2],     s[2 * ksp][3]);
            pa[2] = pack_f16x2(s[2 * ksp + 1][0], s[2 * ksp + 1][1]);
            pa[3] = pack_f16x2(s[2 * ksp + 1][2], s[2 * ksp + 1][3]);
#pragma unroll
            for (int nf = 0; nf < 8; nf++) {
                uint2 vb = Vw[(ksp * 8 + nf) * 32 + lane];
                mma_f16(o[nf], pa, (const uint32_t*)&vb);
            }
        }
        __syncthreads();   // stage reuse protection
    }

    // ---- epilogue: normalize and scatter to g_att [B,S,E]
    const int b = bh >> 4, h = bh & 15;
    const float inv0 = 1.0f / l0, inv1 = 1.0f / l1;
    const int srow0 = qt * 128 + warp * 16 + lr;
    float* base0 = g_att + ((size_t)b * SS + srow0) * EE + h * DD;
    float* base1 = base0 + (size_t)8 * EE;
#pragma unroll
    for (int nf = 0; nf < 8; nf++) {
        float2 v0 = {o[nf][0] * inv0, o[nf][1] * inv0};
        float2 v1 = {o[nf][2] * inv1, o[nf][3] * inv1};
        *(float2*)(base0 + nf * 8 + 2 * lt) = v0;
        *(float2*)(base1 + nf * 8 + 2 * lt) = v1;
    }
}

// ---------------------------------------------------------------------------
extern "C" void kernel_launch(void* const* d_in, const int* in_sizes, int n_in,
                              void* d_out, int out_size)
{
    const float* x     = (const float*)d_in[0];
    const float* w_qkv = (const float*)d_in[1];
    const float* b_qkv = (const float*)d_in[2];
    const float* w_out = (const float*)d_in[3];
    const float* b_out = (const float*)d_in[4];
    float* out = (float*)d_out;

    (void)in_sizes; (void)n_in; (void)out_size;

    cudaFuncSetAttribute(bf16_gemm<0>,
                         cudaFuncAttributeMaxDynamicSharedMemorySize, GEMM_SMEM);
    cudaFuncSetAttribute(bf16_gemm<1>,
                         cudaFuncAttributeMaxDynamicSharedMemorySize, GEMM_SMEM);
    cudaFuncSetAttribute(fa_tf32,
                         cudaFuncAttributeMaxDynamicSharedMemorySize, FA_SMEM);

    // 1) split + fragment-pack x and w_qkv
    prep_a<0><<<BS * 512 / 256, 256>>>(x);
    prep_b<0><<<512 * N_QKV / 256, 256>>>(w_qkv);
    // 2) QKV projection (split-bf16 HMMA) -> attention fragment buffers
    {
        dim3 grid(N_QKV / 128, BS / 128);
        bf16_gemm<0><<<grid, 256, GEMM_SMEM>>>(b_qkv, nullptr);
    }
    // 3) attention (tf32 QK + fp16 PV, fragment-fed, no in-loop STS)
    {
        dim3 grid(SS / 128, BB * HH);
        fa_tf32<<<grid, 256, FA_SMEM>>>();
    }
    // 4) split + fragment-pack att output and w_out
    prep_a<1><<<BS * 512 / 256, 256>>>(nullptr);
    prep_b<1><<<512 * EE / 256, 256>>>(w_out);
    // 5) output projection (split-bf16 HMMA)
    {
        dim3 grid(EE / 128, BS / 128);
        bf16_gemm<1><<<grid, 256, GEMM_SMEM>>>(b_out, out);
    }
}

// round 12
// speedup vs baseline: 1.8861x; 1.1127x over previous
#include <cuda_runtime.h>
#include <cuda_bf16.h>
#include <cuda_fp16.h>
#include <cstdint>

// Problem constants
#define BB 4
#define SS 2048
#define CC 1024
#define EE 1024
#define HH 16
#define DD 64
#define BS (BB * SS)        // 8192
#define N_QKV (3 * EE)      // 3072

// Fragment-packed attention operands (written by QKV GEMM epilogue):
// Q (fp16, pre-scaled x0.125): per (bh, qt128): 8192 halves
//   [ks4(k16)][mb8][lane32][4 regs x f16x2]   (m16n8k16 A-fragments)
// K (fp16): per (bh, kt64): 4096 halves [ks4][nf8][lane32][2 regs x f16x2]
// V (fp16): per (bh, kt64): first 8192 B of a 16384-B slot (R10 layout)
__device__ __half g_qh[BB * HH * 16 * 8192];
__device__ __half g_kh[BB * HH * 32 * 4096];
__device__ __half g_vf[BB * HH * 32 * 8192];

// bf16 split GEMM operands, mma-fragment order (R7 layout, validated).
// g_ah/g_al double as: x fragments (for QKV GEMM), then attention-output
// fragments written by fa's epilogue (for the out-proj GEMM).
__device__ __nv_bfloat16 g_ah[BS * CC],     g_al[BS * CC];
__device__ __nv_bfloat16 g_wqh[CC * N_QKV], g_wql[CC * N_QKV];
__device__ __nv_bfloat16 g_woh[CC * EE],    g_wol[CC * EE];

// ---------------------------------------------------------------------------
// Helpers
// ---------------------------------------------------------------------------
__device__ __forceinline__ uint32_t smem_u32(const void* p) {
    uint32_t a;
    asm("{ .reg .u64 t; cvta.to.shared.u64 t, %1; cvt.u32.u64 %0, t; }"
        : "=r"(a) : "l"(p));
    return a;
}
__device__ __forceinline__ void cp16(uint32_t s, const void* gp) {
    uint64_t g;
    asm("cvta.to.global.u64 %0, %1;" : "=l"(g) : "l"(gp));
    asm volatile("cp.async.cg.shared.global [%0], [%1], 16;" :: "r"(s), "l"(g) : "memory");
}
__device__ __forceinline__ void mma_bf16(float* d, const uint32_t* a,
                                         const uint32_t* b) {
    asm volatile(
        "mma.sync.aligned.m16n8k16.row.col.f32.bf16.bf16.f32 "
        "{%0,%1,%2,%3}, {%4,%5,%6,%7}, {%8,%9}, {%0,%1,%2,%3};"
        : "+f"(d[0]), "+f"(d[1]), "+f"(d[2]), "+f"(d[3])
        : "r"(a[0]), "r"(a[1]), "r"(a[2]), "r"(a[3]), "r"(b[0]), "r"(b[1]));
}
__device__ __forceinline__ void mma_f16(float* d, const uint32_t* a,
                                        const uint32_t* b) {
    asm volatile(
        "mma.sync.aligned.m16n8k16.row.col.f32.f16.f16.f32 "
        "{%0,%1,%2,%3}, {%4,%5,%6,%7}, {%8,%9}, {%0,%1,%2,%3};"
        : "+f"(d[0]), "+f"(d[1]), "+f"(d[2]), "+f"(d[3])
        : "r"(a[0]), "r"(a[1]), "r"(a[2]), "r"(a[3]), "r"(b[0]), "r"(b[1]));
}
// pack (lo, hi) -> f16x2 word
__device__ __forceinline__ uint32_t pack_f16x2(float lo, float hi) {
    uint32_t r;
    asm("cvt.rn.f16x2.f32 %0, %1, %2;" : "=r"(r) : "f"(hi), "f"(lo));
    return r;
}
__device__ __forceinline__ unsigned pack_bf16_hi(float x, float y) {
    __nv_bfloat16 h0 = __float2bfloat16(x);
    __nv_bfloat16 h1 = __float2bfloat16(y);
    return (unsigned)__bfloat16_as_ushort(h0) |
           ((unsigned)__bfloat16_as_ushort(h1) << 16);
}
__device__ __forceinline__ unsigned pack_bf16_lo(float x, float y) {
    float hx = __bfloat162float(__float2bfloat16(x));
    float hy = __bfloat162float(__float2bfloat16(y));
    __nv_bfloat16 l0 = __float2bfloat16(x - hx);
    __nv_bfloat16 l1 = __float2bfloat16(y - hy);
    return (unsigned)__bfloat16_as_ushort(l0) |
           ((unsigned)__bfloat16_as_ushort(l1) << 16);
}

// ---------------------------------------------------------------------------
// Prep kernels (x and weights only; att fragments come from fa's epilogue)
// ---------------------------------------------------------------------------
__global__ __launch_bounds__(256) void prep_a(const float* __restrict__ xin)
{
    const int idx = blockIdx.x * 256 + threadIdx.x;
    const int m = idx >> 9;
    const int kp = idx & 511;
    const int k = kp * 2;
    float2 v = *(const float2*)(xin + (size_t)m * CC + k);

    const int mt = m >> 7, mr = m & 127;
    const int kc = k >> 6, kl6 = k & 63;
    const int ks = kl6 >> 4, kl = kl6 & 15;
    const int mb = mr >> 4, r = mr & 15;
    const int lane = (r & 7) * 4 + ((kl & 7) >> 1);
    const int reg = (r >> 3) + 2 * (kl >> 3);
    const size_t byte = (size_t)(mt * 16 + kc) * 16384 +
                        (size_t)((ks * 8 + mb) * 32 + lane) * 16 + reg * 4;
    *(unsigned*)((char*)g_ah + byte) = pack_bf16_hi(v.x, v.y);
    *(unsigned*)((char*)g_al + byte) = pack_bf16_lo(v.x, v.y);
}

template <int MODE>
__global__ __launch_bounds__(256) void prep_b(const float* __restrict__ w)
{
    constexpr int N = (MODE == 0) ? N_QKV : EE;
    const int idx = blockIdx.x * 256 + threadIdx.x;
    const int kp = idx / N;
    const int n = idx - kp * N;
    const int k = kp * 2;
    const float w0 = w[(size_t)k * N + n];
    const float w1 = w[(size_t)(k + 1) * N + n];

    const int nt = n >> 7, nr = n & 127;
    const int kc = k >> 6, kl6 = k & 63;
    const int ks = kl6 >> 4, kl = kl6 & 15;
    const int nb = nr >> 3, gr = nr & 7;
    const int lane = gr * 4 + ((kl & 7) >> 1);
    const int reg = kl >> 3;
    const size_t byte = (size_t)(nt * 16 + kc) * 16384 +
                        (size_t)((ks * 16 + nb) * 32 + lane) * 8 + reg * 4;
    if (MODE == 0) {
        *(unsigned*)((char*)g_wqh + byte) = pack_bf16_hi(w0, w1);
        *(unsigned*)((char*)g_wql + byte) = pack_bf16_lo(w0, w1);
    } else {
        *(unsigned*)((char*)g_woh + byte) = pack_bf16_hi(w0, w1);
        *(unsigned*)((char*)g_wol + byte) = pack_bf16_lo(w0, w1);
    }
}

// ---------------------------------------------------------------------------
// Split-bf16 HMMA GEMM. MODE 0 epilogue writes Q/K (fp16 k16 fragments) and
// V (fp16, R10 layout). MODE 1 writes the final output.
// ---------------------------------------------------------------------------
#define GEMM_SMEM (2 * 65536)

template <int MODE>
__global__ __launch_bounds__(256, 1) void bf16_gemm(
    const float* __restrict__ bias, float* __restrict__ Cout)
{
    extern __shared__ __align__(128) char tsm[];
    const uint32_t sbase = smem_u32(tsm);

    const int t = threadIdx.x;
    const int lane = t & 31;
    const int warp = t >> 5;
    const int wm = warp & 1;
    const int wn = warp >> 1;
    const int lr = lane >> 2;
    const int lt = lane & 3;
    const int bx = blockIdx.x, by = blockIdx.y;

    const char* Ah = (const char*)g_ah;
    const char* Al = (const char*)g_al;
    const char* Bh = (MODE == 0) ? (const char*)g_wqh : (const char*)g_woh;
    const char* Bl = (MODE == 0) ? (const char*)g_wql : (const char*)g_wol;
    const size_t aoff = (size_t)by * 16 * 16384;
    const size_t boff = (size_t)bx * 16 * 16384;

    float acc[4][4][4];
#pragma unroll
    for (int mf = 0; mf < 4; mf++)
#pragma unroll
        for (int nf = 0; nf < 4; nf++)
#pragma unroll
            for (int r = 0; r < 4; r++) acc[mf][nf][r] = 0.0f;

    auto issue = [&](int c) {
        const uint32_t sdst = sbase + (c & 1) * 65536;
        const char* ga0 = Ah + aoff + (size_t)c * 16384;
        const char* ga1 = Al + aoff + (size_t)c * 16384;
        const char* gb0 = Bh + boff + (size_t)c * 16384;
        const char* gb1 = Bl + boff + (size_t)c * 16384;
#pragma unroll
        for (int i = 0; i < 4; i++) {
            const int o = (t + i * 256) * 16;
            cp16(sdst + o,         ga0 + o);
            cp16(sdst + 16384 + o, ga1 + o);
            cp16(sdst + 32768 + o, gb0 + o);
            cp16(sdst + 49152 + o, gb1 + o);
        }
        asm volatile("cp.async.commit_group;" ::: "memory");
    };

    issue(0);
    for (int c = 0; c < 16; ++c) {
        if (c + 1 < 16) {
            issue(c + 1);
            asm volatile("cp.async.wait_group 1;" ::: "memory");
        } else {
            asm volatile("cp.async.wait_group 0;" ::: "memory");
        }
        __syncthreads();

        const char* sa = tsm + (c & 1) * 65536;
#pragma unroll
        for (int ks = 0; ks < 4; ks++) {
            uint4 ah[4], al[4];
#pragma unroll
            for (int mf = 0; mf < 4; mf++) {
                const int off = ((ks * 8 + wm * 4 + mf) * 32 + lane) * 16;
                ah[mf] = *(const uint4*)(sa + off);
                al[mf] = *(const uint4*)(sa + 16384 + off);
            }
            uint2 bh[4], bl[4];
#pragma unroll
            for (int nf = 0; nf < 4; nf++) {
                const int off = ((ks * 16 + wn * 4 + nf) * 32 + lane) * 8;
                bh[nf] = *(const uint2*)(sa + 32768 + off);
                bl[nf] = *(const uint2*)(sa + 49152 + off);
            }
#pragma unroll
            for (int mf = 0; mf < 4; mf++)
#pragma unroll
                for (int nf = 0; nf < 4; nf++) {
                    mma_bf16(acc[mf][nf], &ah[mf].x, &bh[nf].x);
                    mma_bf16(acc[mf][nf], &al[mf].x, &bh[nf].x);
                    mma_bf16(acc[mf][nf], &ah[mf].x, &bl[nf].x);
                }
        }
        __syncthreads();
    }

    if (MODE == 0) {
        const int part = bx >> 3;
#pragma unroll
        for (int nf = 0; nf < 4; nf++) {
            const int col = bx * 128 + wn * 32 + nf * 8 + 2 * lt;
            const float bi0 = bias[col], bi1 = bias[col + 1];
            const int e = col & 1023;
            const int h = e >> 6, d0 = e & 63;
            const int ks2 = d0 >> 4, kl2 = d0 & 15;   // kl2 even
#pragma unroll
            for (int mf = 0; mf < 4; mf++) {
#pragma unroll
                for (int half = 0; half < 2; half++) {
                    const int row = by * 128 + wm * 64 + mf * 16 + lr + half * 8;
                    const int b = row >> 11, s = row & 2047;
                    const float v0 = acc[mf][nf][half * 2 + 0] + bi0;
                    const float v1 = acc[mf][nf][half * 2 + 1] + bi1;
                    if (part == 0) {
                        // Q fp16 A-fragment store (x0.125)
                        const int qt = s >> 7, r128 = s & 127;
                        const int mb = r128 >> 4, rr = r128 & 15;
                        uint32_t* base = (uint32_t*)(g_qh +
                            ((size_t)(b * HH + h) * 16 + qt) * 8192);
                        const int lane2 = (rr & 7) * 4 + ((kl2 & 7) >> 1);
                        const int reg = (kl2 >> 3) * 2 + (rr >> 3);
                        base[((ks2 * 8 + mb) * 32 + lane2) * 4 + reg] =
                            pack_f16x2(v0 * 0.125f, v1 * 0.125f);
                    } else if (part == 1) {
                        // K fp16 B-fragment store
                        const int kt = s >> 6, seq = s & 63;
                        const int nfk = seq >> 3, lrk = seq & 7;
                        uint32_t* base = (uint32_t*)(g_kh +
                            ((size_t)(b * HH + h) * 32 + kt) * 4096);
                        base[((ks2 * 8 + nfk) * 32 + lrk * 4 +
                              ((kl2 & 7) >> 1)) * 2 + (kl2 >> 3)] =
                            pack_f16x2(v0, v1);
                    } else {
                        // V fp16 store (R10 layout, validated)
                        const int kt = s >> 6, seq = s & 63;
                        const int ksp = seq >> 4, kl = seq & 15;
                        __half* base = g_vf +
                            ((size_t)(b * HH + h) * 32 + kt) * 8192;
#pragma unroll
                        for (int c2 = 0; c2 < 2; c2++) {
                            const int d = d0 + c2;
                            const float val = c2 ? v1 : v0;
                            const int idx =
                                ((((ksp * 8 + (d >> 3)) * 32 +
                                   (d & 7) * 4 + ((kl & 7) >> 1)) * 2 +
                                  (kl >> 3)) << 1) + (kl & 1);
                            base[idx] = __float2half_rn(val);
                        }
                    }
                }
            }
        }
    } else {
#pragma unroll
        for (int nf = 0; nf < 4; nf++) {
            const int col = bx * 128 + wn * 32 + nf * 8 + 2 * lt;
            const float bi0 = bias[col], bi1 = bias[col + 1];
#pragma unroll
            for (int mf = 0; mf < 4; mf++) {
#pragma unroll
                for (int half = 0; half < 2; half++) {
                    const int row = by * 128 + wm * 64 + mf * 16 + lr + half * 8;
                    float2 v;
                    v.x = acc[mf][nf][half * 2 + 0] + bi0;
                    v.y = acc[mf][nf][half * 2 + 1] + bi1;
                    *(float2*)&Cout[(size_t)row * EE + col] = v;
                }
            }
        }
    }
}

// ---------------------------------------------------------------------------
// Flash attention. QK: fp16 m16n8k16 from pre-packed fragments. PV: fp16
// m16n8k16, P packed register-only. Epilogue writes out-proj bf16 hi/lo
// A-fragments directly (no g_att, no repack pass).
// smem: Q 16KB | 2 stages x (K 8KB + V 8KB) = 48KB.
// ---------------------------------------------------------------------------
#define FA_SMEM (16384 + 2 * 16384)   // 49152

__global__ __launch_bounds__(256, 2) void fa_attn()
{
    extern __shared__ __align__(16) char fsm[];
    const uint32_t sb = smem_u32(fsm);

    const int qt = blockIdx.x;                // 0..15
    const int bh = blockIdx.y;                // 0..63
    const int t = threadIdx.x;
    const int lane = t & 31, warp = t >> 5;
    const int lr = lane >> 2, lt = lane & 3;

    const char* gq = (const char*)(g_qh + ((size_t)bh * 16 + qt) * 8192);
    const char* gk = (const char*)(g_kh + (size_t)bh * 32 * 4096);
    const char* gv = (const char*)(g_vf + (size_t)bh * 32 * 8192);

    // prologue: Q tile (16KB) as its own group
#pragma unroll
    for (int i = 0; i < 4; i++)
        cp16(sb + i * 4096 + t * 16, gq + i * 4096 + t * 16);
    asm volatile("cp.async.commit_group;" ::: "memory");

    auto issue = [&](int kt) {
        const uint32_t sd = sb + 16384 + (kt & 1) * 16384;
        const char* kp = gk + (size_t)kt * 8192;
        const char* vp = gv + (size_t)kt * 16384;   // first 8192 B valid
#pragma unroll
        for (int i = 0; i < 2; i++) {
            cp16(sd + i * 4096 + t * 16,        kp + i * 4096 + t * 16);
            cp16(sd + 8192 + i * 4096 + t * 16, vp + i * 4096 + t * 16);
        }
        asm volatile("cp.async.commit_group;" ::: "memory");
    };
    issue(0);

    float m0 = -1e30f, m1 = -1e30f, l0 = 0.0f, l1 = 0.0f;
    float o[8][4];
#pragma unroll
    for (int nf = 0; nf < 8; nf++)
#pragma unroll
        for (int r = 0; r < 4; r++) o[nf][r] = 0.0f;

    for (int kt = 0; kt < SS / 64; kt++) {
        if (kt + 1 < SS / 64) {
            issue(kt + 1);
            asm volatile("cp.async.wait_group 1;" ::: "memory");
        } else {
            asm volatile("cp.async.wait_group 0;" ::: "memory");
        }
        __syncthreads();

        const char* st = fsm + 16384 + (kt & 1) * 16384;
        const uint2* Vw = (const uint2*)(st + 8192);

        // ---- S = Q K^T (fp16 m16n8k16; m16 x n64, k=64)
        float s[8][4];
#pragma unroll
        for (int nf = 0; nf < 8; nf++)
#pragma unroll
            for (int r = 0; r < 4; r++) s[nf][r] = 0.0f;

#pragma unroll
        for (int ks = 0; ks < 4; ks++) {
            uint4 qa = *(const uint4*)(fsm + ((ks * 8 + warp) * 32 + lane) * 16);
#pragma unroll
            for (int nf = 0; nf < 8; nf++) {
                uint2 kb = *(const uint2*)(st + ((ks * 8 + nf) * 32 + lane) * 8);
                mma_f16(s[nf], (const uint32_t*)&qa, (const uint32_t*)&kb);
            }
        }

        // ---- online softmax (rows lr, lr+8); p kept in s[][]
        float rm0 = -1e30f, rm1 = -1e30f;
#pragma unroll
        for (int nf = 0; nf < 8; nf++) {
            rm0 = fmaxf(rm0, fmaxf(s[nf][0], s[nf][1]));
            rm1 = fmaxf(rm1, fmaxf(s[nf][2], s[nf][3]));
        }
        rm0 = fmaxf(rm0, __shfl_xor_sync(0xffffffffu, rm0, 1));
        rm0 = fmaxf(rm0, __shfl_xor_sync(0xffffffffu, rm0, 2));
        rm1 = fmaxf(rm1, __shfl_xor_sync(0xffffffffu, rm1, 1));
        rm1 = fmaxf(rm1, __shfl_xor_sync(0xffffffffu, rm1, 2));
        const float nm0 = fmaxf(m0, rm0), nm1 = fmaxf(m1, rm1);
        float rs0 = 0.0f, rs1 = 0.0f;
#pragma unroll
        for (int nf = 0; nf < 8; nf++) {
            float p0 = __expf(s[nf][0] - nm0);
            float p1 = __expf(s[nf][1] - nm0);
            float p2 = __expf(s[nf][2] - nm1);
            float p3 = __expf(s[nf][3] - nm1);
            rs0 += p0 + p1;
            rs1 += p2 + p3;
            s[nf][0] = p0; s[nf][1] = p1; s[nf][2] = p2; s[nf][3] = p3;
        }
        rs0 += __shfl_xor_sync(0xffffffffu, rs0, 1);
        rs0 += __shfl_xor_sync(0xffffffffu, rs0, 2);
        rs1 += __shfl_xor_sync(0xffffffffu, rs1, 1);
        rs1 += __shfl_xor_sync(0xffffffffu, rs1, 2);
        const float al0 = __expf(m0 - nm0), al1 = __expf(m1 - nm1);
        l0 = l0 * al0 + rs0;
        l1 = l1 * al1 + rs1;
        m0 = nm0; m1 = nm1;
#pragma unroll
        for (int nf = 0; nf < 8; nf++) {
            o[nf][0] *= al0; o[nf][1] *= al0;
            o[nf][2] *= al1; o[nf][3] *= al1;
        }

        // ---- O += P V (fp16 m16n8k16; P packed from S C-frag, register-only)
#pragma unroll
        for (int ksp = 0; ksp < 4; ksp++) {
            uint32_t pa[4];
            pa[0] = pack_f16x2(s[2 * ksp][0],     s[2 * ksp][1]);
            pa[1] = pack_f16x2(s[2 * ksp][2],     s[2 * ksp][3]);
            pa[2] = pack_f16x2(s[2 * ksp + 1][0], s[2 * ksp + 1][1]);
            pa[3] = pack_f16x2(s[2 * ksp + 1][2], s[2 * ksp + 1][3]);
#pragma unroll
            for (int nf = 0; nf < 8; nf++) {
                uint2 vb = Vw[(ksp * 8 + nf) * 32 + lane];
                mma_f16(o[nf], pa, (const uint32_t*)&vb);
            }
        }
        __syncthreads();   // stage reuse protection
    }

    // ---- epilogue: normalize, pack as bf16 hi/lo out-proj A-fragments.
    // m0r = global row; r=lr (row-half 0) and lr+8 (row-half 1); mb=warp.
    const int b = bh >> 4, h = bh & 15;
    const float inv0 = 1.0f / l0, inv1 = 1.0f / l1;
    const int m0r = b * SS + qt * 128 + warp * 16 + lr;
    const int mt = m0r >> 7;
#pragma unroll
    for (int nf = 0; nf < 8; nf++) {
        const float v00 = o[nf][0] * inv0, v01 = o[nf][1] * inv0;
        const float v10 = o[nf][2] * inv1, v11 = o[nf][3] * inv1;
        // k = h*64 + nf*8 + 2lt  ->  kc=h, ks2=nf>>1, reg-pair=nf&1, lane2=lane
        const size_t off = (size_t)(mt * 16 + h) * 16384 +
                           (size_t)(((nf >> 1) * 8 + warp) * 32 + lane) * 16 +
                           (nf & 1) * 8;
        *(unsigned*)((char*)g_ah + off)     = pack_bf16_hi(v00, v01);
        *(unsigned*)((char*)g_al + off)     = pack_bf16_lo(v00, v01);
        *(unsigned*)((char*)g_ah + off + 4) = pack_bf16_hi(v10, v11);
        *(unsigned*)((char*)g_al + off + 4) = pack_bf16_lo(v10, v11);
    }
}

// ---------------------------------------------------------------------------
extern "C" void kernel_launch(void* const* d_in, const int* in_sizes, int n_in,
                              void* d_out, int out_size)
{
    const float* x     = (const float*)d_in[0];
    const float* w_qkv = (const float*)d_in[1];
    const float* b_qkv = (const float*)d_in[2];
    const float* w_out = (const float*)d_in[3];
    const float* b_out = (const float*)d_in[4];
    float* out = (float*)d_out;

    (void)in_sizes; (void)n_in; (void)out_size;

    cudaFuncSetAttribute(bf16_gemm<0>,
                         cudaFuncAttributeMaxDynamicSharedMemorySize, GEMM_SMEM);
    cudaFuncSetAttribute(bf16_gemm<1>,
                         cudaFuncAttributeMaxDynamicSharedMemorySize, GEMM_SMEM);
    cudaFuncSetAttribute(fa_attn,
                         cudaFuncAttributeMaxDynamicSharedMemorySize, FA_SMEM);

    // 1) split + fragment-pack x and both weight matrices
    prep_a<<<BS * 512 / 256, 256>>>(x);
    prep_b<0><<<512 * N_QKV / 256, 256>>>(w_qkv);
    prep_b<1><<<512 * EE / 256, 256>>>(w_out);
    // 2) QKV projection (split-bf16 HMMA) -> fp16 attention fragments
    {
        dim3 grid(N_QKV / 128, BS / 128);
        bf16_gemm<0><<<grid, 256, GEMM_SMEM>>>(b_qkv, nullptr);
    }
    // 3) attention (fp16 QK + fp16 PV) -> out-proj A-fragments
    {
        dim3 grid(SS / 128, BB * HH);
        fa_attn<<<grid, 256, FA_SMEM>>>();
    }
    // 4) output projection (split-bf16 HMMA)
    {
        dim3 grid(EE / 128, BS / 128);
        bf16_gemm<1><<<grid, 256, GEMM_SMEM>>>(b_out, out);
    }
}

// round 14
// speedup vs baseline: 2.1401x; 1.1347x over previous
#include <cuda_runtime.h>
#include <cuda_bf16.h>
#include <cuda_fp16.h>
#include <cstdint>

// Problem constants
#define BB 4
#define SS 2048
#define CC 1024
#define EE 1024
#define HH 16
#define DD 64
#define BS (BB * SS)        // 8192
#define N_QKV (3 * EE)      // 3072

// Fragment-packed attention operands (written by QKV GEMM epilogue):
// Q (fp16, pre-scaled x0.125): per (bh, qt128): 8192 halves
//   [ks4(k16)][mb8][lane32][4 regs x f16x2]   (m16n8k16 A-fragments)
// K (fp16): per (bh, kt64): 4096 halves [ks4][nf8][lane32][2 regs x f16x2]
// V (fp16): per (bh, kt64): first 8192 B of a 16384-B slot (R10 layout)
__device__ __half g_qh[BB * HH * 16 * 8192];
__device__ __half g_kh[BB * HH * 32 * 4096];
__device__ __half g_vf[BB * HH * 32 * 8192];

// tf32 fragment operands for the QKV GEMM (single-pass):
// A (x): per (mt64, kc16): 8192 floats [ks8][mb8][lane32][4 regs]
// B (w_qkv^T): per (nt24, kc16): 8192 floats [ks8][nb16][lane32][2 regs]
//   (linear index uses ks*16+nb — 16 nb blocks per ks!)
__device__ float g_xa[BS * CC];
__device__ float g_wq[CC * N_QKV];

// bf16 split operands for the out-proj GEMM (full accuracy, R7 layout).
// g_ah/g_al are written by fa's epilogue (attention output A-fragments).
__device__ __nv_bfloat16 g_ah[BS * EE], g_al[BS * EE];
__device__ __nv_bfloat16 g_woh[EE * EE], g_wol[EE * EE];

// ---------------------------------------------------------------------------
// Helpers
// ---------------------------------------------------------------------------
__device__ __forceinline__ uint32_t smem_u32(const void* p) {
    uint32_t a;
    asm("{ .reg .u64 t; cvta.to.shared.u64 t, %1; cvt.u32.u64 %0, t; }"
        : "=r"(a) : "l"(p));
    return a;
}
__device__ __forceinline__ void cp16(uint32_t s, const void* gp) {
    uint64_t g;
    asm("cvta.to.global.u64 %0, %1;" : "=l"(g) : "l"(gp));
    asm volatile("cp.async.cg.shared.global [%0], [%1], 16;" :: "r"(s), "l"(g) : "memory");
}
__device__ __forceinline__ void mma_bf16(float* d, const uint32_t* a,
                                         const uint32_t* b) {
    asm volatile(
        "mma.sync.aligned.m16n8k16.row.col.f32.bf16.bf16.f32 "
        "{%0,%1,%2,%3}, {%4,%5,%6,%7}, {%8,%9}, {%0,%1,%2,%3};"
        : "+f"(d[0]), "+f"(d[1]), "+f"(d[2]), "+f"(d[3])
        : "r"(a[0]), "r"(a[1]), "r"(a[2]), "r"(a[3]), "r"(b[0]), "r"(b[1]));
}
__device__ __forceinline__ void mma_f16(float* d, const uint32_t* a,
                                        const uint32_t* b) {
    asm volatile(
        "mma.sync.aligned.m16n8k16.row.col.f32.f16.f16.f32 "
        "{%0,%1,%2,%3}, {%4,%5,%6,%7}, {%8,%9}, {%0,%1,%2,%3};"
        : "+f"(d[0]), "+f"(d[1]), "+f"(d[2]), "+f"(d[3])
        : "r"(a[0]), "r"(a[1]), "r"(a[2]), "r"(a[3]), "r"(b[0]), "r"(b[1]));
}
__device__ __forceinline__ void mma_tf32(float* d, const unsigned* a,
                                         const unsigned* b) {
    asm volatile(
        "mma.sync.aligned.m16n8k8.row.col.f32.tf32.tf32.f32 "
        "{%0,%1,%2,%3}, {%4,%5,%6,%7}, {%8,%9}, {%0,%1,%2,%3};"
        : "+f"(d[0]), "+f"(d[1]), "+f"(d[2]), "+f"(d[3])
        : "r"(a[0]), "r"(a[1]), "r"(a[2]), "r"(a[3]), "r"(b[0]), "r"(b[1]));
}
__device__ __forceinline__ unsigned f2tf(float x) {
    unsigned u;
    asm("cvt.rna.tf32.f32 %0, %1;" : "=r"(u) : "f"(x));
    return u;
}
__device__ __forceinline__ float f2tff(float x) {
    return __uint_as_float(f2tf(x));
}
// pack (lo, hi) -> f16x2 word
__device__ __forceinline__ uint32_t pack_f16x2(float lo, float hi) {
    uint32_t r;
    asm("cvt.rn.f16x2.f32 %0, %1, %2;" : "=r"(r) : "f"(hi), "f"(lo));
    return r;
}
__device__ __forceinline__ unsigned pack_bf16_hi(float x, float y) {
    __nv_bfloat16 h0 = __float2bfloat16(x);
    __nv_bfloat16 h1 = __float2bfloat16(y);
    return (unsigned)__bfloat16_as_ushort(h0) |
           ((unsigned)__bfloat16_as_ushort(h1) << 16);
}
__device__ __forceinline__ unsigned pack_bf16_lo(float x, float y) {
    float hx = __bfloat162float(__float2bfloat16(x));
    float hy = __bfloat162float(__float2bfloat16(y));
    __nv_bfloat16 l0 = __float2bfloat16(x - hx);
    __nv_bfloat16 l1 = __float2bfloat16(y - hy);
    return (unsigned)__bfloat16_as_ushort(l0) |
           ((unsigned)__bfloat16_as_ushort(l1) << 16);
}

// ---------------------------------------------------------------------------
// Prep kernels
// ---------------------------------------------------------------------------
// x -> tf32 m16n8k8 A-fragments
__global__ __launch_bounds__(256) void prep_xa(const float* __restrict__ xin)
{
    const int idx = blockIdx.x * 256 + threadIdx.x;   // < BS*512
    const int m = idx >> 9;
    const int kp = idx & 511;
    const int k = kp * 2;
    float2 v = *(const float2*)(xin + (size_t)m * CC + k);

    const int mt = m >> 7, mr = m & 127;
    const int mb = mr >> 4, rr = mr & 15;
    const int kc = k >> 6, k6 = k & 63;
    const int ks = k6 >> 3, kl = k6 & 7;              // kl even
    const int lane = (rr & 7) * 4 + (kl & 3);
    const int reg = (rr >> 3) + 2 * (kl >> 2);
    float* base = g_xa + (size_t)(mt * 16 + kc) * 8192;
    base[((ks * 8 + mb) * 32 + lane) * 4 + reg]       = f2tff(v.x);
    base[((ks * 8 + mb) * 32 + lane + 1) * 4 + reg]   = f2tff(v.y);
}

// w_qkv [1024][3072] -> tf32 m16n8k8 B-fragments (transposed [n][k])
// Layout per (nt, kc): [ks8][nb16][lane32][2 regs]  (stride: ks*16 + nb!)
__global__ __launch_bounds__(256) void prep_wq(const float* __restrict__ w)
{
    const int idx = blockIdx.x * 256 + threadIdx.x;   // < 512*N_QKV
    const int kp = idx / N_QKV;
    const int n = idx - kp * N_QKV;
    const int k = kp * 2;
    const float w0 = w[(size_t)k * N_QKV + n];
    const float w1 = w[(size_t)(k + 1) * N_QKV + n];

    const int nt = n >> 7, nr = n & 127;
    const int nb = nr >> 3, gr = nr & 7;
    const int kc = k >> 6, k6 = k & 63;
    const int ks = k6 >> 3, kl = k6 & 7;              // kl even
    const int lane = gr * 4 + (kl & 3);
    const int reg = kl >> 2;
    float* base = g_wq + (size_t)(nt * 16 + kc) * 8192;
    base[((ks * 16 + nb) * 32 + lane) * 2 + reg]      = f2tff(w0);
    base[((ks * 16 + nb) * 32 + lane + 1) * 2 + reg]  = f2tff(w1);
}

// w_out -> bf16 hi/lo fragments (R7 layout)
__global__ __launch_bounds__(256) void prep_wo(const float* __restrict__ w)
{
    const int idx = blockIdx.x * 256 + threadIdx.x;   // < 512*EE
    const int kp = idx / EE;
    const int n = idx - kp * EE;
    const int k = kp * 2;
    const float w0 = w[(size_t)k * EE + n];
    const float w1 = w[(size_t)(k + 1) * EE + n];

    const int nt = n >> 7, nr = n & 127;
    const int kc = k >> 6, kl6 = k & 63;
    const int ks = kl6 >> 4, kl = kl6 & 15;
    const int nb = nr >> 3, gr = nr & 7;
    const int lane = gr * 4 + ((kl & 7) >> 1);
    const int reg = kl >> 3;
    const size_t byte = (size_t)(nt * 16 + kc) * 16384 +
                        (size_t)((ks * 16 + nb) * 32 + lane) * 8 + reg * 4;
    *(unsigned*)((char*)g_woh + byte) = pack_bf16_hi(w0, w1);
    *(unsigned*)((char*)g_wol + byte) = pack_bf16_lo(w0, w1);
}

// ---------------------------------------------------------------------------
// Single-pass tf32 QKV GEMM. CTA tile 128x128, K in 16 chunks of 64,
// 256 threads (8 warps, warp tile 64x32). 2 x 64KB cp.async stages.
// Epilogue writes Q/K (fp16 k16 fragments) and V (fp16 R10 layout).
// ---------------------------------------------------------------------------
#define QKV_SMEM (2 * 65536)

__global__ __launch_bounds__(256, 1) void tf32_gemm(const float* __restrict__ bias)
{
    extern __shared__ __align__(128) char tsm[];
    const uint32_t sbase = smem_u32(tsm);

    const int t = threadIdx.x;
    const int lane = t & 31;
    const int warp = t >> 5;
    const int wm = warp & 1;
    const int wn = warp >> 1;
    const int lr = lane >> 2;
    const int lt = lane & 3;
    const int bx = blockIdx.x, by = blockIdx.y;

    const char* Ag = (const char*)(g_xa + (size_t)by * 16 * 8192);
    const char* Bg = (const char*)(g_wq + (size_t)bx * 16 * 8192);

    float acc[4][4][4];
#pragma unroll
    for (int mf = 0; mf < 4; mf++)
#pragma unroll
        for (int nf = 0; nf < 4; nf++)
#pragma unroll
            for (int r = 0; r < 4; r++) acc[mf][nf][r] = 0.0f;

    auto issue = [&](int c) {
        const uint32_t sdst = sbase + (c & 1) * 65536;
        const char* ga = Ag + (size_t)c * 32768;
        const char* gb = Bg + (size_t)c * 32768;
#pragma unroll
        for (int i = 0; i < 8; i++) {
            const int o = (t + i * 256) * 16;
            cp16(sdst + o,         ga + o);
            cp16(sdst + 32768 + o, gb + o);
        }
        asm volatile("cp.async.commit_group;" ::: "memory");
    };

    issue(0);
    for (int c = 0; c < 16; ++c) {
        if (c + 1 < 16) {
            issue(c + 1);
            asm volatile("cp.async.wait_group 1;" ::: "memory");
        } else {
            asm volatile("cp.async.wait_group 0;" ::: "memory");
        }
        __syncthreads();

        const char* sa = tsm + (c & 1) * 65536;
        const char* sbB = sa + 32768;
#pragma unroll
        for (int ks = 0; ks < 8; ks++) {
            uint4 af[4];
#pragma unroll
            for (int mf = 0; mf < 4; mf++)
                af[mf] = *(const uint4*)(sa +
                    ((ks * 8 + wm * 4 + mf) * 32 + lane) * 16);
            uint2 bf[4];
#pragma unroll
            for (int nf = 0; nf < 4; nf++)
                bf[nf] = *(const uint2*)(sbB +
                    ((ks * 16 + wn * 4 + nf) * 32 + lane) * 8);
#pragma unroll
            for (int mf = 0; mf < 4; mf++)
#pragma unroll
                for (int nf = 0; nf < 4; nf++)
                    mma_tf32(acc[mf][nf], (const unsigned*)&af[mf],
                             (const unsigned*)&bf[nf]);
        }
        __syncthreads();
    }

    // Epilogue: +bias, write fp16 attention fragments (validated R12 layout)
    const int part = bx >> 3;
#pragma unroll
    for (int nf = 0; nf < 4; nf++) {
        const int col = bx * 128 + wn * 32 + nf * 8 + 2 * lt;
        const float bi0 = bias[col], bi1 = bias[col + 1];
        const int e = col & 1023;
        const int h = e >> 6, d0 = e & 63;
        const int ks2 = d0 >> 4, kl2 = d0 & 15;   // kl2 even
#pragma unroll
        for (int mf = 0; mf < 4; mf++) {
#pragma unroll
            for (int half = 0; half < 2; half++) {
                const int row = by * 128 + wm * 64 + mf * 16 + lr + half * 8;
                const int b = row >> 11, s = row & 2047;
                const float v0 = acc[mf][nf][half * 2 + 0] + bi0;
                const float v1 = acc[mf][nf][half * 2 + 1] + bi1;
                if (part == 0) {
                    const int qt = s >> 7, r128 = s & 127;
                    const int mb = r128 >> 4, rr = r128 & 15;
                    uint32_t* base = (uint32_t*)(g_qh +
                        ((size_t)(b * HH + h) * 16 + qt) * 8192);
                    const int lane2 = (rr & 7) * 4 + ((kl2 & 7) >> 1);
                    const int reg = (kl2 >> 3) * 2 + (rr >> 3);
                    base[((ks2 * 8 + mb) * 32 + lane2) * 4 + reg] =
                        pack_f16x2(v0 * 0.125f, v1 * 0.125f);
                } else if (part == 1) {
                    const int kt = s >> 6, seq = s & 63;
                    const int nfk = seq >> 3, lrk = seq & 7;
                    uint32_t* base = (uint32_t*)(g_kh +
                        ((size_t)(b * HH + h) * 32 + kt) * 4096);
                    base[((ks2 * 8 + nfk) * 32 + lrk * 4 +
                          ((kl2 & 7) >> 1)) * 2 + (kl2 >> 3)] =
                        pack_f16x2(v0, v1);
                } else {
                    const int kt = s >> 6, seq = s & 63;
                    const int ksp = seq >> 4, kl = seq & 15;
                    __half* base = g_vf +
                        ((size_t)(b * HH + h) * 32 + kt) * 8192;
#pragma unroll
                    for (int c2 = 0; c2 < 2; c2++) {
                        const int d = d0 + c2;
                        const float val = c2 ? v1 : v0;
                        const int idx =
                            ((((ksp * 8 + (d >> 3)) * 32 +
                               (d & 7) * 4 + ((kl & 7) >> 1)) * 2 +
                              (kl >> 3)) << 1) + (kl & 1);
                        base[idx] = __float2half_rn(val);
                    }
                }
            }
        }
    }
}

// ---------------------------------------------------------------------------
// Split-bf16 HMMA out-proj GEMM (full accuracy; writes final output).
// ---------------------------------------------------------------------------
#define GEMM_SMEM (2 * 65536)

__global__ __launch_bounds__(256, 1) void bf16_gemm_out(
    const float* __restrict__ bias, float* __restrict__ Cout)
{
    extern __shared__ __align__(128) char tsm[];
    const uint32_t sbase = smem_u32(tsm);

    const int t = threadIdx.x;
    const int lane = t & 31;
    const int warp = t >> 5;
    const int wm = warp & 1;
    const int wn = warp >> 1;
    const int lr = lane >> 2;
    const int lt = lane & 3;
    const int bx = blockIdx.x, by = blockIdx.y;

    const char* Ah = (const char*)g_ah;
    const char* Al = (const char*)g_al;
    const char* Bh = (const char*)g_woh;
    const char* Bl = (const char*)g_wol;
    const size_t aoff = (size_t)by * 16 * 16384;
    const size_t boff = (size_t)bx * 16 * 16384;

    float acc[4][4][4];
#pragma unroll
    for (int mf = 0; mf < 4; mf++)
#pragma unroll
        for (int nf = 0; nf < 4; nf++)
#pragma unroll
            for (int r = 0; r < 4; r++) acc[mf][nf][r] = 0.0f;

    auto issue = [&](int c) {
        const uint32_t sdst = sbase + (c & 1) * 65536;
        const char* ga0 = Ah + aoff + (size_t)c * 16384;
        const char* ga1 = Al + aoff + (size_t)c * 16384;
        const char* gb0 = Bh + boff + (size_t)c * 16384;
        const char* gb1 = Bl + boff + (size_t)c * 16384;
#pragma unroll
        for (int i = 0; i < 4; i++) {
            const int o = (t + i * 256) * 16;
            cp16(sdst + o,         ga0 + o);
            cp16(sdst + 16384 + o, ga1 + o);
            cp16(sdst + 32768 + o, gb0 + o);
            cp16(sdst + 49152 + o, gb1 + o);
        }
        asm volatile("cp.async.commit_group;" ::: "memory");
    };

    issue(0);
    for (int c = 0; c < 16; ++c) {
        if (c + 1 < 16) {
            issue(c + 1);
            asm volatile("cp.async.wait_group 1;" ::: "memory");
        } else {
            asm volatile("cp.async.wait_group 0;" ::: "memory");
        }
        __syncthreads();

        const char* sa = tsm + (c & 1) * 65536;
#pragma unroll
        for (int ks = 0; ks < 4; ks++) {
            uint4 ah[4], al[4];
#pragma unroll
            for (int mf = 0; mf < 4; mf++) {
                const int off = ((ks * 8 + wm * 4 + mf) * 32 + lane) * 16;
                ah[mf] = *(const uint4*)(sa + off);
                al[mf] = *(const uint4*)(sa + 16384 + off);
            }
            uint2 bh[4], bl[4];
#pragma unroll
            for (int nf = 0; nf < 4; nf++) {
                const int off = ((ks * 16 + wn * 4 + nf) * 32 + lane) * 8;
                bh[nf] = *(const uint2*)(sa + 32768 + off);
                bl[nf] = *(const uint2*)(sa + 49152 + off);
            }
#pragma unroll
            for (int mf = 0; mf < 4; mf++)
#pragma unroll
                for (int nf = 0; nf < 4; nf++) {
                    mma_bf16(acc[mf][nf], &ah[mf].x, &bh[nf].x);
                    mma_bf16(acc[mf][nf], &al[mf].x, &bh[nf].x);
                    mma_bf16(acc[mf][nf], &ah[mf].x, &bl[nf].x);
                }
        }
        __syncthreads();
    }

#pragma unroll
    for (int nf = 0; nf < 4; nf++) {
        const int col = bx * 128 + wn * 32 + nf * 8 + 2 * lt;
        const float bi0 = bias[col], bi1 = bias[col + 1];
#pragma unroll
        for (int mf = 0; mf < 4; mf++) {
#pragma unroll
            for (int half = 0; half < 2; half++) {
                const int row = by * 128 + wm * 64 + mf * 16 + lr + half * 8;
                float2 v;
                v.x = acc[mf][nf][half * 2 + 0] + bi0;
                v.y = acc[mf][nf][half * 2 + 1] + bi1;
                *(float2*)&Cout[(size_t)row * EE + col] = v;
            }
        }
    }
}

// ---------------------------------------------------------------------------
// Flash attention (unchanged from R12). fp16 QK + fp16 PV, register-only P,
// epilogue writes out-proj bf16 hi/lo A-fragments.
// ---------------------------------------------------------------------------
#define FA_SMEM (16384 + 2 * 16384)   // 49152

__global__ __launch_bounds__(256, 2) void fa_attn()
{
    extern __shared__ __align__(16) char fsm[];
    const uint32_t sb = smem_u32(fsm);

    const int qt = blockIdx.x;                // 0..15
    const int bh = blockIdx.y;                // 0..63
    const int t = threadIdx.x;
    const int lane = t & 31, warp = t >> 5;
    const int lr = lane >> 2, lt = lane & 3;

    const char* gq = (const char*)(g_qh + ((size_t)bh * 16 + qt) * 8192);
    const char* gk = (const char*)(g_kh + (size_t)bh * 32 * 4096);
    const char* gv = (const char*)(g_vf + (size_t)bh * 32 * 8192);

#pragma unroll
    for (int i = 0; i < 4; i++)
        cp16(sb + i * 4096 + t * 16, gq + i * 4096 + t * 16);
    asm volatile("cp.async.commit_group;" ::: "memory");

    auto issue = [&](int kt) {
        const uint32_t sd = sb + 16384 + (kt & 1) * 16384;
        const char* kp = gk + (size_t)kt * 8192;
        const char* vp = gv + (size_t)kt * 16384;
#pragma unroll
        for (int i = 0; i < 2; i++) {
            cp16(sd + i * 4096 + t * 16,        kp + i * 4096 + t * 16);
            cp16(sd + 8192 + i * 4096 + t * 16, vp + i * 4096 + t * 16);
        }
        asm volatile("cp.async.commit_group;" ::: "memory");
    };
    issue(0);

    float m0 = -1e30f, m1 = -1e30f, l0 = 0.0f, l1 = 0.0f;
    float o[8][4];
#pragma unroll
    for (int nf = 0; nf < 8; nf++)
#pragma unroll
        for (int r = 0; r < 4; r++) o[nf][r] = 0.0f;

    for (int kt = 0; kt < SS / 64; kt++) {
        if (kt + 1 < SS / 64) {
            issue(kt + 1);
            asm volatile("cp.async.wait_group 1;" ::: "memory");
        } else {
            asm volatile("cp.async.wait_group 0;" ::: "memory");
        }
        __syncthreads();

        const char* st = fsm + 16384 + (kt & 1) * 16384;
        const uint2* Vw = (const uint2*)(st + 8192);

        float s[8][4];
#pragma unroll
        for (int nf = 0; nf < 8; nf++)
#pragma unroll
            for (int r = 0; r < 4; r++) s[nf][r] = 0.0f;

#pragma unroll
        for (int ks = 0; ks < 4; ks++) {
            uint4 qa = *(const uint4*)(fsm + ((ks * 8 + warp) * 32 + lane) * 16);
#pragma unroll
            for (int nf = 0; nf < 8; nf++) {
                uint2 kb = *(const uint2*)(st + ((ks * 8 + nf) * 32 + lane) * 8);
                mma_f16(s[nf], (const uint32_t*)&qa, (const uint32_t*)&kb);
            }
        }

        float rm0 = -1e30f, rm1 = -1e30f;
#pragma unroll
        for (int nf = 0; nf < 8; nf++) {
            rm0 = fmaxf(rm0, fmaxf(s[nf][0], s[nf][1]));
            rm1 = fmaxf(rm1, fmaxf(s[nf][2], s[nf][3]));
        }
        rm0 = fmaxf(rm0, __shfl_xor_sync(0xffffffffu, rm0, 1));
        rm0 = fmaxf(rm0, __shfl_xor_sync(0xffffffffu, rm0, 2));
        rm1 = fmaxf(rm1, __shfl_xor_sync(0xffffffffu, rm1, 1));
        rm1 = fmaxf(rm1, __shfl_xor_sync(0xffffffffu, rm1, 2));
        const float nm0 = fmaxf(m0, rm0), nm1 = fmaxf(m1, rm1);
        float rs0 = 0.0f, rs1 = 0.0f;
#pragma unroll
        for (int nf = 0; nf < 8; nf++) {
            float p0 = __expf(s[nf][0] - nm0);
            float p1 = __expf(s[nf][1] - nm0);
            float p2 = __expf(s[nf][2] - nm1);
            float p3 = __expf(s[nf][3] - nm1);
            rs0 += p0 + p1;
            rs1 += p2 + p3;
            s[nf][0] = p0; s[nf][1] = p1; s[nf][2] = p2; s[nf][3] = p3;
        }
        rs0 += __shfl_xor_sync(0xffffffffu, rs0, 1);
        rs0 += __shfl_xor_sync(0xffffffffu, rs0, 2);
        rs1 += __shfl_xor_sync(0xffffffffu, rs1, 1);
        rs1 += __shfl_xor_sync(0xffffffffu, rs1, 2);
        const float al0 = __expf(m0 - nm0), al1 = __expf(m1 - nm1);
        l0 = l0 * al0 + rs0;
        l1 = l1 * al1 + rs1;
        m0 = nm0; m1 = nm1;
#pragma unroll
        for (int nf = 0; nf < 8; nf++) {
            o[nf][0] *= al0; o[nf][1] *= al0;
            o[nf][2] *= al1; o[nf][3] *= al1;
        }

#pragma unroll
        for (int ksp = 0; ksp < 4; ksp++) {
            uint32_t pa[4];
            pa[0] = pack_f16x2(s[2 * ksp][0],     s[2 * ksp][1]);
            pa[1] = pack_f16x2(s[2 * ksp][2],     s[2 * ksp][3]);
            pa[2] = pack_f16x2(s[2 * ksp + 1][0], s[2 * ksp + 1][1]);
            pa[3] = pack_f16x2(s[2 * ksp + 1][2], s[2 * ksp + 1][3]);
#pragma unroll
            for (int nf = 0; nf < 8; nf++) {
                uint2 vb = Vw[(ksp * 8 + nf) * 32 + lane];
                mma_f16(o[nf], pa, (const uint32_t*)&vb);
            }
        }
        __syncthreads();
    }

    const int b = bh >> 4, h = bh & 15;
    const float inv0 = 1.0f / l0, inv1 = 1.0f / l1;
    const int m0r = b * SS + qt * 128 + warp * 16 + lr;
    const int mt = m0r >> 7;
#pragma unroll
    for (int nf = 0; nf < 8; nf++) {
        const float v00 = o[nf][0] * inv0, v01 = o[nf][1] * inv0;
        const float v10 = o[nf][2] * inv1, v11 = o[nf][3] * inv1;
        const size_t off = (size_t)(mt * 16 + h) * 16384 +
                           (size_t)(((nf >> 1) * 8 + warp) * 32 + lane) * 16 +
                           (nf & 1) * 8;
        *(unsigned*)((char*)g_ah + off)     = pack_bf16_hi(v00, v01);
        *(unsigned*)((char*)g_al + off)     = pack_bf16_lo(v00, v01);
        *(unsigned*)((char*)g_ah + off + 4) = pack_bf16_hi(v10, v11);
        *(unsigned*)((char*)g_al + off + 4) = pack_bf16_lo(v10, v11);
    }
}

// ---------------------------------------------------------------------------
extern "C" void kernel_launch(void* const* d_in, const int* in_sizes, int n_in,
                              void* d_out, int out_size)
{
    const float* x     = (const float*)d_in[0];
    const float* w_qkv = (const float*)d_in[1];
    const float* b_qkv = (const float*)d_in[2];
    const float* w_out = (const float*)d_in[3];
    const float* b_out = (const float*)d_in[4];
    float* out = (float*)d_out;

    (void)in_sizes; (void)n_in; (void)out_size;

    cudaFuncSetAttribute(tf32_gemm,
                         cudaFuncAttributeMaxDynamicSharedMemorySize, QKV_SMEM);
    cudaFuncSetAttribute(bf16_gemm_out,
                         cudaFuncAttributeMaxDynamicSharedMemorySize, GEMM_SMEM);
    cudaFuncSetAttribute(fa_attn,
                         cudaFuncAttributeMaxDynamicSharedMemorySize, FA_SMEM);

    // 1) fragment-pack x (tf32), w_qkv (tf32), w_out (split-bf16)
    prep_xa<<<BS * 512 / 256, 256>>>(x);
    prep_wq<<<512 * N_QKV / 256, 256>>>(w_qkv);
    prep_wo<<<512 * EE / 256, 256>>>(w_out);
    // 2) QKV projection (single-pass tf32 HMMA) -> fp16 attention fragments
    {
        dim3 grid(N_QKV / 128, BS / 128);
        tf32_gemm<<<grid, 256, QKV_SMEM>>>(b_qkv);
    }
    // 3) attention (fp16 QK + fp16 PV) -> out-proj A-fragments
    {
        dim3 grid(SS / 128, BB * HH);
        fa_attn<<<grid, 256, FA_SMEM>>>();
    }
    // 4) output projection (split-bf16 HMMA, full accuracy)
    {
        dim3 grid(EE / 128, BS / 128);
        bf16_gemm_out<<<grid, 256, GEMM_SMEM>>>(b_out, out);
    }
}

// round 16
// speedup vs baseline: 2.2544x; 1.0534x over previous
#include <cuda_runtime.h>
#include <cuda_bf16.h>
#include <cuda_fp16.h>
#include <cstdint>

// Problem constants
#define BB 4
#define SS 2048
#define CC 1024
#define EE 1024
#define HH 16
#define DD 64
#define BS (BB * SS)        // 8192
#define N_QKV (3 * EE)      // 3072

// Fragment-packed attention operands (written by QKV GEMM epilogue):
// Q (fp16, pre-scaled x0.125): per (bh, qt128): 8192 halves
//   [ks4(k16)][mb8][lane32][4 regs x f16x2]   (m16n8k16 A-fragments)
// K (fp16): per (bh, kt64): 4096 halves [ks4][nf8][lane32][2 regs x f16x2]
// V (fp16): per (bh, kt64): first 8192 B of a 16384-B slot (R10 layout)
__device__ __half g_qh[BB * HH * 16 * 8192];
__device__ __half g_kh[BB * HH * 32 * 4096];
__device__ __half g_vf[BB * HH * 32 * 8192];

// tf32 fragment operands for the QKV GEMM (single-pass):
// A (x): per (mt64, kc16): 8192 floats [ks8][mb8][lane32][4 regs]
// B (w_qkv^T): per (nt24, kc16): 8192 floats [ks8][nb16][lane32][2 regs]
// ks-major order means each 32KB chunk splits into two contiguous 16KB
// half-chunks (k 0..31 / k 32..63) — exploited by the 32-deep pipeline.
__device__ float g_xa[BS * CC];
__device__ float g_wq[CC * N_QKV];

// bf16 split operands for the out-proj GEMM (full accuracy, R7 layout).
// g_ah/g_al are written by fa's epilogue (attention output A-fragments).
__device__ __nv_bfloat16 g_ah[BS * EE], g_al[BS * EE];
__device__ __nv_bfloat16 g_woh[EE * EE], g_wol[EE * EE];

// ---------------------------------------------------------------------------
// Helpers
// ---------------------------------------------------------------------------
__device__ __forceinline__ uint32_t smem_u32(const void* p) {
    uint32_t a;
    asm("{ .reg .u64 t; cvta.to.shared.u64 t, %1; cvt.u32.u64 %0, t; }"
        : "=r"(a) : "l"(p));
    return a;
}
__device__ __forceinline__ void cp16(uint32_t s, const void* gp) {
    uint64_t g;
    asm("cvta.to.global.u64 %0, %1;" : "=l"(g) : "l"(gp));
    asm volatile("cp.async.cg.shared.global [%0], [%1], 16;" :: "r"(s), "l"(g) : "memory");
}
__device__ __forceinline__ void mma_bf16(float* d, const uint32_t* a,
                                         const uint32_t* b) {
    asm volatile(
        "mma.sync.aligned.m16n8k16.row.col.f32.bf16.bf16.f32 "
        "{%0,%1,%2,%3}, {%4,%5,%6,%7}, {%8,%9}, {%0,%1,%2,%3};"
        : "+f"(d[0]), "+f"(d[1]), "+f"(d[2]), "+f"(d[3])
        : "r"(a[0]), "r"(a[1]), "r"(a[2]), "r"(a[3]), "r"(b[0]), "r"(b[1]));
}
__device__ __forceinline__ void mma_f16(float* d, const uint32_t* a,
                                        const uint32_t* b) {
    asm volatile(
        "mma.sync.aligned.m16n8k16.row.col.f32.f16.f16.f32 "
        "{%0,%1,%2,%3}, {%4,%5,%6,%7}, {%8,%9}, {%0,%1,%2,%3};"
        : "+f"(d[0]), "+f"(d[1]), "+f"(d[2]), "+f"(d[3])
        : "r"(a[0]), "r"(a[1]), "r"(a[2]), "r"(a[3]), "r"(b[0]), "r"(b[1]));
}
__device__ __forceinline__ void mma_tf32(float* d, const unsigned* a,
                                         const unsigned* b) {
    asm volatile(
        "mma.sync.aligned.m16n8k8.row.col.f32.tf32.tf32.f32 "
        "{%0,%1,%2,%3}, {%4,%5,%6,%7}, {%8,%9}, {%0,%1,%2,%3};"
        : "+f"(d[0]), "+f"(d[1]), "+f"(d[2]), "+f"(d[3])
        : "r"(a[0]), "r"(a[1]), "r"(a[2]), "r"(a[3]), "r"(b[0]), "r"(b[1]));
}
__device__ __forceinline__ unsigned f2tf(float x) {
    unsigned u;
    asm("cvt.rna.tf32.f32 %0, %1;" : "=r"(u) : "f"(x));
    return u;
}
__device__ __forceinline__ float f2tff(float x) {
    return __uint_as_float(f2tf(x));
}
// pack (lo, hi) -> f16x2 word
__device__ __forceinline__ uint32_t pack_f16x2(float lo, float hi) {
    uint32_t r;
    asm("cvt.rn.f16x2.f32 %0, %1, %2;" : "=r"(r) : "f"(hi), "f"(lo));
    return r;
}
__device__ __forceinline__ unsigned pack_bf16_hi(float x, float y) {
    __nv_bfloat16 h0 = __float2bfloat16(x);
    __nv_bfloat16 h1 = __float2bfloat16(y);
    return (unsigned)__bfloat16_as_ushort(h0) |
           ((unsigned)__bfloat16_as_ushort(h1) << 16);
}
__device__ __forceinline__ unsigned pack_bf16_lo(float x, float y) {
    float hx = __bfloat162float(__float2bfloat16(x));
    float hy = __bfloat162float(__float2bfloat16(y));
    __nv_bfloat16 l0 = __float2bfloat16(x - hx);
    __nv_bfloat16 l1 = __float2bfloat16(y - hy);
    return (unsigned)__bfloat16_as_ushort(l0) |
           ((unsigned)__bfloat16_as_ushort(l1) << 16);
}

// ---------------------------------------------------------------------------
// Prep kernels (unchanged from R14)
// ---------------------------------------------------------------------------
__global__ __launch_bounds__(256) void prep_xa(const float* __restrict__ xin)
{
    const int idx = blockIdx.x * 256 + threadIdx.x;   // < BS*512
    const int m = idx >> 9;
    const int kp = idx & 511;
    const int k = kp * 2;
    float2 v = *(const float2*)(xin + (size_t)m * CC + k);

    const int mt = m >> 7, mr = m & 127;
    const int mb = mr >> 4, rr = mr & 15;
    const int kc = k >> 6, k6 = k & 63;
    const int ks = k6 >> 3, kl = k6 & 7;              // kl even
    const int lane = (rr & 7) * 4 + (kl & 3);
    const int reg = (rr >> 3) + 2 * (kl >> 2);
    float* base = g_xa + (size_t)(mt * 16 + kc) * 8192;
    base[((ks * 8 + mb) * 32 + lane) * 4 + reg]       = f2tff(v.x);
    base[((ks * 8 + mb) * 32 + lane + 1) * 4 + reg]   = f2tff(v.y);
}

__global__ __launch_bounds__(256) void prep_wq(const float* __restrict__ w)
{
    const int idx = blockIdx.x * 256 + threadIdx.x;   // < 512*N_QKV
    const int kp = idx / N_QKV;
    const int n = idx - kp * N_QKV;
    const int k = kp * 2;
    const float w0 = w[(size_t)k * N_QKV + n];
    const float w1 = w[(size_t)(k + 1) * N_QKV + n];

    const int nt = n >> 7, nr = n & 127;
    const int nb = nr >> 3, gr = nr & 7;
    const int kc = k >> 6, k6 = k & 63;
    const int ks = k6 >> 3, kl = k6 & 7;              // kl even
    const int lane = gr * 4 + (kl & 3);
    const int reg = kl >> 2;
    float* base = g_wq + (size_t)(nt * 16 + kc) * 8192;
    base[((ks * 16 + nb) * 32 + lane) * 2 + reg]      = f2tff(w0);
    base[((ks * 16 + nb) * 32 + lane + 1) * 2 + reg]  = f2tff(w1);
}

__global__ __launch_bounds__(256) void prep_wo(const float* __restrict__ w)
{
    const int idx = blockIdx.x * 256 + threadIdx.x;   // < 512*EE
    const int kp = idx / EE;
    const int n = idx - kp * EE;
    const int k = kp * 2;
    const float w0 = w[(size_t)k * EE + n];
    const float w1 = w[(size_t)(k + 1) * EE + n];

    const int nt = n >> 7, nr = n & 127;
    const int kc = k >> 6, kl6 = k & 63;
    const int ks = kl6 >> 4, kl = kl6 & 15;
    const int nb = nr >> 3, gr = nr & 7;
    const int lane = gr * 4 + ((kl & 7) >> 1);
    const int reg = kl >> 3;
    const size_t byte = (size_t)(nt * 16 + kc) * 16384 +
                        (size_t)((ks * 16 + nb) * 32 + lane) * 8 + reg * 4;
    *(unsigned*)((char*)g_woh + byte) = pack_bf16_hi(w0, w1);
    *(unsigned*)((char*)g_wol + byte) = pack_bf16_lo(w0, w1);
}

// ---------------------------------------------------------------------------
// Single-pass tf32 QKV GEMM. CTA tile 128x128, K as 32 half-chunks of 32,
// 2 x 32KB cp.async stages -> 64KB smem -> 2 CTAs/SM.
// Epilogue writes Q/K (fp16 k16 fragments) and V (fp16 R10 layout).
// ---------------------------------------------------------------------------
#define QKV_SMEM (2 * 32768)

__global__ __launch_bounds__(256, 2) void tf32_gemm(const float* __restrict__ bias)
{
    extern __shared__ __align__(128) char tsm[];
    const uint32_t sbase = smem_u32(tsm);

    const int t = threadIdx.x;
    const int lane = t & 31;
    const int warp = t >> 5;
    const int wm = warp & 1;
    const int wn = warp >> 1;
    const int lr = lane >> 2;
    const int lt = lane & 3;
    const int bx = blockIdx.x, by = blockIdx.y;

    // half-chunk h (0..31): A bytes [h*16384, +16384), same for B.
    const char* Ag = (const char*)(g_xa + (size_t)by * 16 * 8192);
    const char* Bg = (const char*)(g_wq + (size_t)bx * 16 * 8192);

    float acc[4][4][4];
#pragma unroll
    for (int mf = 0; mf < 4; mf++)
#pragma unroll
        for (int nf = 0; nf < 4; nf++)
#pragma unroll
            for (int r = 0; r < 4; r++) acc[mf][nf][r] = 0.0f;

    auto issue = [&](int c) {
        const uint32_t sdst = sbase + (c & 1) * 32768;
        const char* ga = Ag + (size_t)c * 16384;
        const char* gb = Bg + (size_t)c * 16384;
#pragma unroll
        for (int i = 0; i < 4; i++) {
            const int o = (t + i * 256) * 16;
            cp16(sdst + o,         ga + o);
            cp16(sdst + 16384 + o, gb + o);
        }
        asm volatile("cp.async.commit_group;" ::: "memory");
    };

    issue(0);
    for (int c = 0; c < 32; ++c) {
        if (c + 1 < 32) {
            issue(c + 1);
            asm volatile("cp.async.wait_group 1;" ::: "memory");
        } else {
            asm volatile("cp.async.wait_group 0;" ::: "memory");
        }
        __syncthreads();

        const char* sa = tsm + (c & 1) * 32768;
        const char* sbB = sa + 16384;
#pragma unroll
        for (int ks = 0; ks < 4; ks++) {
            uint4 af[4];
#pragma unroll
            for (int mf = 0; mf < 4; mf++)
                af[mf] = *(const uint4*)(sa +
                    ((ks * 8 + wm * 4 + mf) * 32 + lane) * 16);
            uint2 bf[4];
#pragma unroll
            for (int nf = 0; nf < 4; nf++)
                bf[nf] = *(const uint2*)(sbB +
                    ((ks * 16 + wn * 4 + nf) * 32 + lane) * 8);
#pragma unroll
            for (int mf = 0; mf < 4; mf++)
#pragma unroll
                for (int nf = 0; nf < 4; nf++)
                    mma_tf32(acc[mf][nf], (const unsigned*)&af[mf],
                             (const unsigned*)&bf[nf]);
        }
        __syncthreads();
    }

    // Epilogue: +bias, write fp16 attention fragments (validated R12 layout)
    const int part = bx >> 3;
#pragma unroll
    for (int nf = 0; nf < 4; nf++) {
        const int col = bx * 128 + wn * 32 + nf * 8 + 2 * lt;
        const float bi0 = bias[col], bi1 = bias[col + 1];
        const int e = col & 1023;
        const int h = e >> 6, d0 = e & 63;
        const int ks2 = d0 >> 4, kl2 = d0 & 15;   // kl2 even
#pragma unroll
        for (int mf = 0; mf < 4; mf++) {
#pragma unroll
            for (int half = 0; half < 2; half++) {
                const int row = by * 128 + wm * 64 + mf * 16 + lr + half * 8;
                const int b = row >> 11, s = row & 2047;
                const float v0 = acc[mf][nf][half * 2 + 0] + bi0;
                const float v1 = acc[mf][nf][half * 2 + 1] + bi1;
                if (part == 0) {
                    const int qt = s >> 7, r128 = s & 127;
                    const int mb = r128 >> 4, rr = r128 & 15;
                    uint32_t* base = (uint32_t*)(g_qh +
                        ((size_t)(b * HH + h) * 16 + qt) * 8192);
                    const int lane2 = (rr & 7) * 4 + ((kl2 & 7) >> 1);
                    const int reg = (kl2 >> 3) * 2 + (rr >> 3);
                    base[((ks2 * 8 + mb) * 32 + lane2) * 4 + reg] =
                        pack_f16x2(v0 * 0.125f, v1 * 0.125f);
                } else if (part == 1) {
                    const int kt = s >> 6, seq = s & 63;
                    const int nfk = seq >> 3, lrk = seq & 7;
                    uint32_t* base = (uint32_t*)(g_kh +
                        ((size_t)(b * HH + h) * 32 + kt) * 4096);
                    base[((ks2 * 8 + nfk) * 32 + lrk * 4 +
                          ((kl2 & 7) >> 1)) * 2 + (kl2 >> 3)] =
                        pack_f16x2(v0, v1);
                } else {
                    const int kt = s >> 6, seq = s & 63;
                    const int ksp = seq >> 4, kl = seq & 15;
                    __half* base = g_vf +
                        ((size_t)(b * HH + h) * 32 + kt) * 8192;
#pragma unroll
                    for (int c2 = 0; c2 < 2; c2++) {
                        const int d = d0 + c2;
                        const float val = c2 ? v1 : v0;
                        const int idx =
                            ((((ksp * 8 + (d >> 3)) * 32 +
                               (d & 7) * 4 + ((kl & 7) >> 1)) * 2 +
                              (kl >> 3)) << 1) + (kl & 1);
                        base[idx] = __float2half_rn(val);
                    }
                }
            }
        }
    }
}

// ---------------------------------------------------------------------------
// Split-bf16 HMMA out-proj GEMM. K as 32 half-chunks of 32; stage 32KB
// (Ah 8K | Al 8K | Bh 8K | Bl 8K); 2 stages = 64KB -> 2 CTAs/SM.
// ---------------------------------------------------------------------------
#define GEMM_SMEM (2 * 32768)

__global__ __launch_bounds__(256, 2) void bf16_gemm_out(
    const float* __restrict__ bias, float* __restrict__ Cout)
{
    extern __shared__ __align__(128) char tsm[];
    const uint32_t sbase = smem_u32(tsm);

    const int t = threadIdx.x;
    const int lane = t & 31;
    const int warp = t >> 5;
    const int wm = warp & 1;
    const int wn = warp >> 1;
    const int lr = lane >> 2;
    const int lt = lane & 3;
    const int bx = blockIdx.x, by = blockIdx.y;

    const char* Ah = (const char*)g_ah + (size_t)by * 16 * 16384;
    const char* Al = (const char*)g_al + (size_t)by * 16 * 16384;
    const char* Bh = (const char*)g_woh + (size_t)bx * 16 * 16384;
    const char* Bl = (const char*)g_wol + (size_t)bx * 16 * 16384;

    float acc[4][4][4];
#pragma unroll
    for (int mf = 0; mf < 4; mf++)
#pragma unroll
        for (int nf = 0; nf < 4; nf++)
#pragma unroll
            for (int r = 0; r < 4; r++) acc[mf][nf][r] = 0.0f;

    auto issue = [&](int c) {
        const uint32_t sdst = sbase + (c & 1) * 32768;
        const size_t go = (size_t)c * 8192;
#pragma unroll
        for (int i = 0; i < 2; i++) {
            const int o = (t + i * 256) * 16;
            cp16(sdst + o,         Ah + go + o);
            cp16(sdst + 8192 + o,  Al + go + o);
            cp16(sdst + 16384 + o, Bh + go + o);
            cp16(sdst + 24576 + o, Bl + go + o);
        }
        asm volatile("cp.async.commit_group;" ::: "memory");
    };

    issue(0);
    for (int c = 0; c < 32; ++c) {
        if (c + 1 < 32) {
            issue(c + 1);
            asm volatile("cp.async.wait_group 1;" ::: "memory");
        } else {
            asm volatile("cp.async.wait_group 0;" ::: "memory");
        }
        __syncthreads();

        const char* sa = tsm + (c & 1) * 32768;
#pragma unroll
        for (int ks = 0; ks < 2; ks++) {
            uint4 ah[4], al[4];
#pragma unroll
            for (int mf = 0; mf < 4; mf++) {
                const int off = ((ks * 8 + wm * 4 + mf) * 32 + lane) * 16;
                ah[mf] = *(const uint4*)(sa + off);
                al[mf] = *(const uint4*)(sa + 8192 + off);
            }
            uint2 bh[4], bl[4];
#pragma unroll
            for (int nf = 0; nf < 4; nf++) {
                const int off = ((ks * 16 + wn * 4 + nf) * 32 + lane) * 8;
                bh[nf] = *(const uint2*)(sa + 16384 + off);
                bl[nf] = *(const uint2*)(sa + 24576 + off);
            }
#pragma unroll
            for (int mf = 0; mf < 4; mf++)
#pragma unroll
                for (int nf = 0; nf < 4; nf++) {
                    mma_bf16(acc[mf][nf], &ah[mf].x, &bh[nf].x);
                    mma_bf16(acc[mf][nf], &al[mf].x, &bh[nf].x);
                    mma_bf16(acc[mf][nf], &ah[mf].x, &bl[nf].x);
                }
        }
        __syncthreads();
    }

#pragma unroll
    for (int nf = 0; nf < 4; nf++) {
        const int col = bx * 128 + wn * 32 + nf * 8 + 2 * lt;
        const float bi0 = bias[col], bi1 = bias[col + 1];
#pragma unroll
        for (int mf = 0; mf < 4; mf++) {
#pragma unroll
            for (int half = 0; half < 2; half++) {
                const int row = by * 128 + wm * 64 + mf * 16 + lr + half * 8;
                float2 v;
                v.x = acc[mf][nf][half * 2 + 0] + bi0;
                v.y = acc[mf][nf][half * 2 + 1] + bi1;
                *(float2*)&Cout[(size_t)row * EE + col] = v;
            }
        }
    }
}

// ---------------------------------------------------------------------------
// Flash attention (unchanged from R12). fp16 QK + fp16 PV, register-only P,
// epilogue writes out-proj bf16 hi/lo A-fragments.
// ---------------------------------------------------------------------------
#define FA_SMEM (16384 + 2 * 16384)   // 49152

__global__ __launch_bounds__(256, 2) void fa_attn()
{
    extern __shared__ __align__(16) char fsm[];
    const uint32_t sb = smem_u32(fsm);

    const int qt = blockIdx.x;                // 0..15
    const int bh = blockIdx.y;                // 0..63
    const int t = threadIdx.x;
    const int lane = t & 31, warp = t >> 5;
    const int lr = lane >> 2, lt = lane & 3;

    const char* gq = (const char*)(g_qh + ((size_t)bh * 16 + qt) * 8192);
    const char* gk = (const char*)(g_kh + (size_t)bh * 32 * 4096);
    const char* gv = (const char*)(g_vf + (size_t)bh * 32 * 8192);

#pragma unroll
    for (int i = 0; i < 4; i++)
        cp16(sb + i * 4096 + t * 16, gq + i * 4096 + t * 16);
    asm volatile("cp.async.commit_group;" ::: "memory");

    auto issue = [&](int kt) {
        const uint32_t sd = sb + 16384 + (kt & 1) * 16384;
        const char* kp = gk + (size_t)kt * 8192;
        const char* vp = gv + (size_t)kt * 16384;
#pragma unroll
        for (int i = 0; i < 2; i++) {
            cp16(sd + i * 4096 + t * 16,        kp + i * 4096 + t * 16);
            cp16(sd + 8192 + i * 4096 + t * 16, vp + i * 4096 + t * 16);
        }
        asm volatile("cp.async.commit_group;" ::: "memory");
    };
    issue(0);

    float m0 = -1e30f, m1 = -1e30f, l0 = 0.0f, l1 = 0.0f;
    float o[8][4];
#pragma unroll
    for (int nf = 0; nf < 8; nf++)
#pragma unroll
        for (int r = 0; r < 4; r++) o[nf][r] = 0.0f;

    for (int kt = 0; kt < SS / 64; kt++) {
        if (kt + 1 < SS / 64) {
            issue(kt + 1);
            asm volatile("cp.async.wait_group 1;" ::: "memory");
        } else {
            asm volatile("cp.async.wait_group 0;" ::: "memory");
        }
        __syncthreads();

        const char* st = fsm + 16384 + (kt & 1) * 16384;
        const uint2* Vw = (const uint2*)(st + 8192);

        float s[8][4];
#pragma unroll
        for (int nf = 0; nf < 8; nf++)
#pragma unroll
            for (int r = 0; r < 4; r++) s[nf][r] = 0.0f;

#pragma unroll
        for (int ks = 0; ks < 4; ks++) {
            uint4 qa = *(const uint4*)(fsm + ((ks * 8 + warp) * 32 + lane) * 16);
#pragma unroll
            for (int nf = 0; nf < 8; nf++) {
                uint2 kb = *(const uint2*)(st + ((ks * 8 + nf) * 32 + lane) * 8);
                mma_f16(s[nf], (const uint32_t*)&qa, (const uint32_t*)&kb);
            }
        }

        float rm0 = -1e30f, rm1 = -1e30f;
#pragma unroll
        for (int nf = 0; nf < 8; nf++) {
            rm0 = fmaxf(rm0, fmaxf(s[nf][0], s[nf][1]));
            rm1 = fmaxf(rm1, fmaxf(s[nf][2], s[nf][3]));
        }
        rm0 = fmaxf(rm0, __shfl_xor_sync(0xffffffffu, rm0, 1));
        rm0 = fmaxf(rm0, __shfl_xor_sync(0xffffffffu, rm0, 2));
        rm1 = fmaxf(rm1, __shfl_xor_sync(0xffffffffu, rm1, 1));
        rm1 = fmaxf(rm1, __shfl_xor_sync(0xffffffffu, rm1, 2));
        const float nm0 = fmaxf(m0, rm0), nm1 = fmaxf(m1, rm1);
        float rs0 = 0.0f, rs1 = 0.0f;
#pragma unroll
        for (int nf = 0; nf < 8; nf++) {
            float p0 = __expf(s[nf][0] - nm0);
            float p1 = __expf(s[nf][1] - nm0);
            float p2 = __expf(s[nf][2] - nm1);
            float p3 = __expf(s[nf][3] - nm1);
            rs0 += p0 + p1;
            rs1 += p2 + p3;
            s[nf][0] = p0; s[nf][1] = p1; s[nf][2] = p2; s[nf][3] = p3;
        }
        rs0 += __shfl_xor_sync(0xffffffffu, rs0, 1);
        rs0 += __shfl_xor_sync(0xffffffffu, rs0, 2);
        rs1 += __shfl_xor_sync(0xffffffffu, rs1, 1);
        rs1 += __shfl_xor_sync(0xffffffffu, rs1, 2);
        const float al0 = __expf(m0 - nm0), al1 = __expf(m1 - nm1);
        l0 = l0 * al0 + rs0;
        l1 = l1 * al1 + rs1;
        m0 = nm0; m1 = nm1;
#pragma unroll
        for (int nf = 0; nf < 8; nf++) {
            o[nf][0] *= al0; o[nf][1] *= al0;
            o[nf][2] *= al1; o[nf][3] *= al1;
        }

#pragma unroll
        for (int ksp = 0; ksp < 4; ksp++) {
            uint32_t pa[4];
            pa[0] = pack_f16x2(s[2 * ksp][0],     s[2 * ksp][1]);
            pa[1] = pack_f16x2(s[2 * ksp][2],     s[2 * ksp][3]);
            pa[2] = pack_f16x2(s[2 * ksp + 1][0], s[2 * ksp + 1][1]);
            pa[3] = pack_f16x2(s[2 * ksp + 1][2], s[2 * ksp + 1][3]);
#pragma unroll
            for (int nf = 0; nf < 8; nf++) {
                uint2 vb = Vw[(ksp * 8 + nf) * 32 + lane];
                mma_f16(o[nf], pa, (const uint32_t*)&vb);
            }
        }
        __syncthreads();
    }

    const int b = bh >> 4, h = bh & 15;
    const float inv0 = 1.0f / l0, inv1 = 1.0f / l1;
    const int m0r = b * SS + qt * 128 + warp * 16 + lr;
    const int mt = m0r >> 7;
#pragma unroll
    for (int nf = 0; nf < 8; nf++) {
        const float v00 = o[nf][0] * inv0, v01 = o[nf][1] * inv0;
        const float v10 = o[nf][2] * inv1, v11 = o[nf][3] * inv1;
        const size_t off = (size_t)(mt * 16 + h) * 16384 +
                           (size_t)(((nf >> 1) * 8 + warp) * 32 + lane) * 16 +
                           (nf & 1) * 8;
        *(unsigned*)((char*)g_ah + off)     = pack_bf16_hi(v00, v01);
        *(unsigned*)((char*)g_al + off)     = pack_bf16_lo(v00, v01);
        *(unsigned*)((char*)g_ah + off + 4) = pack_bf16_hi(v10, v11);
        *(unsigned*)((char*)g_al + off + 4) = pack_bf16_lo(v10, v11);
    }
}

// ---------------------------------------------------------------------------
extern "C" void kernel_launch(void* const* d_in, const int* in_sizes, int n_in,
                              void* d_out, int out_size)
{
    const float* x     = (const float*)d_in[0];
    const float* w_qkv = (const float*)d_in[1];
    const float* b_qkv = (const float*)d_in[2];
    const float* w_out = (const float*)d_in[3];
    const float* b_out = (const float*)d_in[4];
    float* out = (float*)d_out;

    (void)in_sizes; (void)n_in; (void)out_size;

    cudaFuncSetAttribute(tf32_gemm,
                         cudaFuncAttributeMaxDynamicSharedMemorySize, QKV_SMEM);
    cudaFuncSetAttribute(bf16_gemm_out,
                         cudaFuncAttributeMaxDynamicSharedMemorySize, GEMM_SMEM);
    cudaFuncSetAttribute(fa_attn,
                         cudaFuncAttributeMaxDynamicSharedMemorySize, FA_SMEM);

    // 1) fragment-pack x (tf32), w_qkv (tf32), w_out (split-bf16)
    prep_xa<<<BS * 512 / 256, 256>>>(x);
    prep_wq<<<512 * N_QKV / 256, 256>>>(w_qkv);
    prep_wo<<<512 * EE / 256, 256>>>(w_out);
    // 2) QKV projection (single-pass tf32 HMMA, 2 CTAs/SM) -> fp16 fragments
    {
        dim3 grid(N_QKV / 128, BS / 128);
        tf32_gemm<<<grid, 256, QKV_SMEM>>>(b_qkv);
    }
    // 3) attention (fp16 QK + fp16 PV) -> out-proj A-fragments
    {
        dim3 grid(SS / 128, BB * HH);
        fa_attn<<<grid, 256, FA_SMEM>>>();
    }
    // 4) output projection (split-bf16 HMMA, 2 CTAs/SM, full accuracy)
    {
        dim3 grid(EE / 128, BS / 128);
        bf16_gemm_out<<<grid, 256, GEMM_SMEM>>>(b_out, out);
    }
}

// round 17
// speedup vs baseline: 3.3191x; 1.4723x over previous
#include <cuda_runtime.h>
#include <cuda_bf16.h>
#include <cuda_fp16.h>
#include <cstdint>

// Problem constants
#define BB 4
#define SS 2048
#define CC 1024
#define EE 1024
#define HH 16
#define DD 64
#define BS (BB * SS)        // 8192
#define N_QKV (3 * EE)      // 3072

// Fragment-packed attention operands (written by QKV GEMM epilogue):
// Q (fp16, x0.125): per (bh, qt128): 8192 halves [ks4][mb8][lane32][4regs f16x2]
// K (fp16): per (bh, kt64): 4096 halves [ks4][nf8][lane32][2regs f16x2]
// V (fp16): per (bh, kt64): first 8192 B of a 16384-B slot (R10 layout)
__device__ __half g_qh[BB * HH * 16 * 8192];
__device__ __half g_kh[BB * HH * 32 * 4096];
__device__ __half g_vf[BB * HH * 32 * 8192];

// fp16 m16n8k16 fragment operands for both GEMMs:
// A chunks (128 rows x 64 k = 16KB): [ks4][mb8][lane32][4 regs x f16x2]
// B chunks (128 n x 64 k = 16KB):    [ks4][nb16][lane32][2 regs x f16x2]
__device__ __half g_xa16[BS * CC];      // x          (QKV A)
__device__ __half g_wq16[CC * N_QKV];   // w_qkv^T    (QKV B)
__device__ __half g_af[BS * EE];        // attn out   (out-proj A, by fa)
__device__ __half g_wo16[EE * EE];      // w_out^T    (out-proj B)

// ---------------------------------------------------------------------------
// Helpers
// ---------------------------------------------------------------------------
__device__ __forceinline__ uint32_t smem_u32(const void* p) {
    uint32_t a;
    asm("{ .reg .u64 t; cvta.to.shared.u64 t, %1; cvt.u32.u64 %0, t; }"
        : "=r"(a) : "l"(p));
    return a;
}
__device__ __forceinline__ void cp16(uint32_t s, const void* gp) {
    uint64_t g;
    asm("cvta.to.global.u64 %0, %1;" : "=l"(g) : "l"(gp));
    asm volatile("cp.async.cg.shared.global [%0], [%1], 16;" :: "r"(s), "l"(g) : "memory");
}
__device__ __forceinline__ void mma_f16(float* d, const uint32_t* a,
                                        const uint32_t* b) {
    asm volatile(
        "mma.sync.aligned.m16n8k16.row.col.f32.f16.f16.f32 "
        "{%0,%1,%2,%3}, {%4,%5,%6,%7}, {%8,%9}, {%0,%1,%2,%3};"
        : "+f"(d[0]), "+f"(d[1]), "+f"(d[2]), "+f"(d[3])
        : "r"(a[0]), "r"(a[1]), "r"(a[2]), "r"(a[3]), "r"(b[0]), "r"(b[1]));
}
// pack (lo, hi) -> f16x2 word
__device__ __forceinline__ uint32_t pack_f16x2(float lo, float hi) {
    uint32_t r;
    asm("cvt.rn.f16x2.f32 %0, %1, %2;" : "=r"(r) : "f"(hi), "f"(lo));
    return r;
}

// ---------------------------------------------------------------------------
// Prep kernels: pack fp32 sources into fp16 m16n8k16 fragment chunks.
// ---------------------------------------------------------------------------
// A-side (x): one thread per (row m, even k) pair -> one f16x2 word.
__global__ __launch_bounds__(256) void prep_xa(const float* __restrict__ xin)
{
    const int idx = blockIdx.x * 256 + threadIdx.x;   // < BS*512
    const int m = idx >> 9;
    const int kp = idx & 511;
    const int k = kp * 2;
    float2 v = *(const float2*)(xin + (size_t)m * CC + k);

    const int mt = m >> 7, mr = m & 127;
    const int mb = mr >> 4, rr = mr & 15;
    const int kc = k >> 6, k6 = k & 63;
    const int ks = k6 >> 4, kl = k6 & 15;             // kl even
    const int lane = (rr & 7) * 4 + ((kl & 7) >> 1);
    const int reg = (kl >> 3) * 2 + (rr >> 3);
    uint32_t* base = (uint32_t*)g_xa16 + (size_t)(mt * 16 + kc) * 4096;
    base[((ks * 8 + mb) * 32 + lane) * 4 + reg] = pack_f16x2(v.x, v.y);
}

// B-side (weights, transposed [n][k]). MODE 0: w_qkv; MODE 1: w_out.
template <int MODE>
__global__ __launch_bounds__(256) void prep_w(const float* __restrict__ w)
{
    constexpr int N = (MODE == 0) ? N_QKV : EE;
    const int idx = blockIdx.x * 256 + threadIdx.x;   // < 512*N
    const int kp = idx / N;
    const int n = idx - kp * N;
    const int k = kp * 2;
    const float w0 = w[(size_t)k * N + n];
    const float w1 = w[(size_t)(k + 1) * N + n];

    const int nt = n >> 7, nr = n & 127;
    const int nb = nr >> 3, gr = nr & 7;
    const int kc = k >> 6, k6 = k & 63;
    const int ks = k6 >> 4, kl = k6 & 15;             // kl even
    const int lane = gr * 4 + ((kl & 7) >> 1);
    const int reg = kl >> 3;
    uint32_t* base = ((MODE == 0) ? (uint32_t*)g_wq16 : (uint32_t*)g_wo16) +
                     (size_t)(nt * 16 + kc) * 4096;
    base[((ks * 16 + nb) * 32 + lane) * 2 + reg] = pack_f16x2(w0, w1);
}

// ---------------------------------------------------------------------------
// Single-pass fp16 m16n8k16 GEMM. CTA tile 128x128, 16 chunks of k64,
// 2 x 32KB cp.async stages (A 16K | B 16K) -> 2 CTAs/SM.
// MODE 0: A=x frags, B=w_qkv frags; epilogue writes Q/K/V fp16 fragments.
// MODE 1: A=attn frags, B=w_out frags; epilogue +bias -> out.
// ---------------------------------------------------------------------------
#define GEMM_SMEM (2 * 32768)

template <int MODE>
__global__ __launch_bounds__(256, 2) void f16_gemm(
    const float* __restrict__ bias, float* __restrict__ Cout)
{
    extern __shared__ __align__(128) char tsm[];
    const uint32_t sbase = smem_u32(tsm);

    const int t = threadIdx.x;
    const int lane = t & 31;
    const int warp = t >> 5;
    const int wm = warp & 1;
    const int wn = warp >> 1;
    const int lr = lane >> 2;
    const int lt = lane & 3;
    const int bx = blockIdx.x, by = blockIdx.y;

    const char* Ag = (MODE == 0) ? (const char*)g_xa16 : (const char*)g_af;
    const char* Bg = (MODE == 0) ? (const char*)g_wq16 : (const char*)g_wo16;
    Ag += (size_t)by * 16 * 16384;
    Bg += (size_t)bx * 16 * 16384;

    float acc[4][4][4];
#pragma unroll
    for (int mf = 0; mf < 4; mf++)
#pragma unroll
        for (int nf = 0; nf < 4; nf++)
#pragma unroll
            for (int r = 0; r < 4; r++) acc[mf][nf][r] = 0.0f;

    auto issue = [&](int c) {
        const uint32_t sdst = sbase + (c & 1) * 32768;
        const char* ga = Ag + (size_t)c * 16384;
        const char* gb = Bg + (size_t)c * 16384;
#pragma unroll
        for (int i = 0; i < 4; i++) {
            const int o = (t + i * 256) * 16;
            cp16(sdst + o,         ga + o);
            cp16(sdst + 16384 + o, gb + o);
        }
        asm volatile("cp.async.commit_group;" ::: "memory");
    };

    issue(0);
    for (int c = 0; c < 16; ++c) {
        if (c + 1 < 16) {
            issue(c + 1);
            asm volatile("cp.async.wait_group 1;" ::: "memory");
        } else {
            asm volatile("cp.async.wait_group 0;" ::: "memory");
        }
        __syncthreads();

        const char* sa = tsm + (c & 1) * 32768;
        const char* sbB = sa + 16384;
#pragma unroll
        for (int ks = 0; ks < 4; ks++) {
            uint4 af[4];
#pragma unroll
            for (int mf = 0; mf < 4; mf++)
                af[mf] = *(const uint4*)(sa +
                    ((ks * 8 + wm * 4 + mf) * 32 + lane) * 16);
            uint2 bf[4];
#pragma unroll
            for (int nf = 0; nf < 4; nf++)
                bf[nf] = *(const uint2*)(sbB +
                    ((ks * 16 + wn * 4 + nf) * 32 + lane) * 8);
#pragma unroll
            for (int mf = 0; mf < 4; mf++)
#pragma unroll
                for (int nf = 0; nf < 4; nf++)
                    mma_f16(acc[mf][nf], (const uint32_t*)&af[mf],
                            (const uint32_t*)&bf[nf]);
        }
        __syncthreads();
    }

    if (MODE == 0) {
        // Epilogue: +bias, write fp16 attention fragments (validated layout)
        const int part = bx >> 3;
#pragma unroll
        for (int nf = 0; nf < 4; nf++) {
            const int col = bx * 128 + wn * 32 + nf * 8 + 2 * lt;
            const float bi0 = bias[col], bi1 = bias[col + 1];
            const int e = col & 1023;
            const int h = e >> 6, d0 = e & 63;
            const int ks2 = d0 >> 4, kl2 = d0 & 15;   // kl2 even
#pragma unroll
            for (int mf = 0; mf < 4; mf++) {
#pragma unroll
                for (int half = 0; half < 2; half++) {
                    const int row = by * 128 + wm * 64 + mf * 16 + lr + half * 8;
                    const int b = row >> 11, s = row & 2047;
                    const float v0 = acc[mf][nf][half * 2 + 0] + bi0;
                    const float v1 = acc[mf][nf][half * 2 + 1] + bi1;
                    if (part == 0) {
                        const int qt = s >> 7, r128 = s & 127;
                        const int mb = r128 >> 4, rr = r128 & 15;
                        uint32_t* base = (uint32_t*)(g_qh +
                            ((size_t)(b * HH + h) * 16 + qt) * 8192);
                        const int lane2 = (rr & 7) * 4 + ((kl2 & 7) >> 1);
                        const int reg = (kl2 >> 3) * 2 + (rr >> 3);
                        base[((ks2 * 8 + mb) * 32 + lane2) * 4 + reg] =
                            pack_f16x2(v0 * 0.125f, v1 * 0.125f);
                    } else if (part == 1) {
                        const int kt = s >> 6, seq = s & 63;
                        const int nfk = seq >> 3, lrk = seq & 7;
                        uint32_t* base = (uint32_t*)(g_kh +
                            ((size_t)(b * HH + h) * 32 + kt) * 4096);
                        base[((ks2 * 8 + nfk) * 32 + lrk * 4 +
                              ((kl2 & 7) >> 1)) * 2 + (kl2 >> 3)] =
                            pack_f16x2(v0, v1);
                    } else {
                        const int kt = s >> 6, seq = s & 63;
                        const int ksp = seq >> 4, kl = seq & 15;
                        __half* base = g_vf +
                            ((size_t)(b * HH + h) * 32 + kt) * 8192;
#pragma unroll
                        for (int c2 = 0; c2 < 2; c2++) {
                            const int d = d0 + c2;
                            const float val = c2 ? v1 : v0;
                            const int idx =
                                ((((ksp * 8 + (d >> 3)) * 32 +
                                   (d & 7) * 4 + ((kl & 7) >> 1)) * 2 +
                                  (kl >> 3)) << 1) + (kl & 1);
                            base[idx] = __float2half_rn(val);
                        }
                    }
                }
            }
        }
    } else {
#pragma unroll
        for (int nf = 0; nf < 4; nf++) {
            const int col = bx * 128 + wn * 32 + nf * 8 + 2 * lt;
            const float bi0 = bias[col], bi1 = bias[col + 1];
#pragma unroll
            for (int mf = 0; mf < 4; mf++) {
#pragma unroll
                for (int half = 0; half < 2; half++) {
                    const int row = by * 128 + wm * 64 + mf * 16 + lr + half * 8;
                    float2 v;
                    v.x = acc[mf][nf][half * 2 + 0] + bi0;
                    v.y = acc[mf][nf][half * 2 + 1] + bi1;
                    *(float2*)&Cout[(size_t)row * EE + col] = v;
                }
            }
        }
    }
}

// ---------------------------------------------------------------------------
// Flash attention. fp16 QK + fp16 PV, register-only P; epilogue writes
// out-proj fp16 A-fragments (g_af). smem: Q 16KB | 2 x 16KB stages.
// ---------------------------------------------------------------------------
#define FA_SMEM (16384 + 2 * 16384)   // 49152

__global__ __launch_bounds__(256, 2) void fa_attn()
{
    extern __shared__ __align__(16) char fsm[];
    const uint32_t sb = smem_u32(fsm);

    const int qt = blockIdx.x;                // 0..15
    const int bh = blockIdx.y;                // 0..63
    const int t = threadIdx.x;
    const int lane = t & 31, warp = t >> 5;
    const int lr = lane >> 2, lt = lane & 3;

    const char* gq = (const char*)(g_qh + ((size_t)bh * 16 + qt) * 8192);
    const char* gk = (const char*)(g_kh + (size_t)bh * 32 * 4096);
    const char* gv = (const char*)(g_vf + (size_t)bh * 32 * 8192);

#pragma unroll
    for (int i = 0; i < 4; i++)
        cp16(sb + i * 4096 + t * 16, gq + i * 4096 + t * 16);
    asm volatile("cp.async.commit_group;" ::: "memory");

    auto issue = [&](int kt) {
        const uint32_t sd = sb + 16384 + (kt & 1) * 16384;
        const char* kp = gk + (size_t)kt * 8192;
        const char* vp = gv + (size_t)kt * 16384;
#pragma unroll
        for (int i = 0; i < 2; i++) {
            cp16(sd + i * 4096 + t * 16,        kp + i * 4096 + t * 16);
            cp16(sd + 8192 + i * 4096 + t * 16, vp + i * 4096 + t * 16);
        }
        asm volatile("cp.async.commit_group;" ::: "memory");
    };
    issue(0);

    float m0 = -1e30f, m1 = -1e30f, l0 = 0.0f, l1 = 0.0f;
    float o[8][4];
#pragma unroll
    for (int nf = 0; nf < 8; nf++)
#pragma unroll
        for (int r = 0; r < 4; r++) o[nf][r] = 0.0f;

    for (int kt = 0; kt < SS / 64; kt++) {
        if (kt + 1 < SS / 64) {
            issue(kt + 1);
            asm volatile("cp.async.wait_group 1;" ::: "memory");
        } else {
            asm volatile("cp.async.wait_group 0;" ::: "memory");
        }
        __syncthreads();

        const char* st = fsm + 16384 + (kt & 1) * 16384;
        const uint2* Vw = (const uint2*)(st + 8192);

        float s[8][4];
#pragma unroll
        for (int nf = 0; nf < 8; nf++)
#pragma unroll
            for (int r = 0; r < 4; r++) s[nf][r] = 0.0f;

#pragma unroll
        for (int ks = 0; ks < 4; ks++) {
            uint4 qa = *(const uint4*)(fsm + ((ks * 8 + warp) * 32 + lane) * 16);
#pragma unroll
            for (int nf = 0; nf < 8; nf++) {
                uint2 kb = *(const uint2*)(st + ((ks * 8 + nf) * 32 + lane) * 8);
                mma_f16(s[nf], (const uint32_t*)&qa, (const uint32_t*)&kb);
            }
        }

        float rm0 = -1e30f, rm1 = -1e30f;
#pragma unroll
        for (int nf = 0; nf < 8; nf++) {
            rm0 = fmaxf(rm0, fmaxf(s[nf][0], s[nf][1]));
            rm1 = fmaxf(rm1, fmaxf(s[nf][2], s[nf][3]));
        }
        rm0 = fmaxf(rm0, __shfl_xor_sync(0xffffffffu, rm0, 1));
        rm0 = fmaxf(rm0, __shfl_xor_sync(0xffffffffu, rm0, 2));
        rm1 = fmaxf(rm1, __shfl_xor_sync(0xffffffffu, rm1, 1));
        rm1 = fmaxf(rm1, __shfl_xor_sync(0xffffffffu, rm1, 2));
        const float nm0 = fmaxf(m0, rm0), nm1 = fmaxf(m1, rm1);
        float rs0 = 0.0f, rs1 = 0.0f;
#pragma unroll
        for (int nf = 0; nf < 8; nf++) {
            float p0 = __expf(s[nf][0] - nm0);
            float p1 = __expf(s[nf][1] - nm0);
            float p2 = __expf(s[nf][2] - nm1);
            float p3 = __expf(s[nf][3] - nm1);
            rs0 += p0 + p1;
            rs1 += p2 + p3;
            s[nf][0] = p0; s[nf][1] = p1; s[nf][2] = p2; s[nf][3] = p3;
        }
        rs0 += __shfl_xor_sync(0xffffffffu, rs0, 1);
        rs0 += __shfl_xor_sync(0xffffffffu, rs0, 2);
        rs1 += __shfl_xor_sync(0xffffffffu, rs1, 1);
        rs1 += __shfl_xor_sync(0xffffffffu, rs1, 2);
        const float al0 = __expf(m0 - nm0), al1 = __expf(m1 - nm1);
        l0 = l0 * al0 + rs0;
        l1 = l1 * al1 + rs1;
        m0 = nm0; m1 = nm1;
#pragma unroll
        for (int nf = 0; nf < 8; nf++) {
            o[nf][0] *= al0; o[nf][1] *= al0;
            o[nf][2] *= al1; o[nf][3] *= al1;
        }

#pragma unroll
        for (int ksp = 0; ksp < 4; ksp++) {
            uint32_t pa[4];
            pa[0] = pack_f16x2(s[2 * ksp][0],     s[2 * ksp][1]);
            pa[1] = pack_f16x2(s[2 * ksp][2],     s[2 * ksp][3]);
            pa[2] = pack_f16x2(s[2 * ksp + 1][0], s[2 * ksp + 1][1]);
            pa[3] = pack_f16x2(s[2 * ksp + 1][2], s[2 * ksp + 1][3]);
#pragma unroll
            for (int nf = 0; nf < 8; nf++) {
                uint2 vb = Vw[(ksp * 8 + nf) * 32 + lane];
                mma_f16(o[nf], pa, (const uint32_t*)&vb);
            }
        }
        __syncthreads();
    }

    // Epilogue: normalize, write fp16 m16n8k16 A-fragments for out-proj.
    // k = h*64 + nf*8 + 2lt -> kc=h, ks=nf>>1, reg=(nf&1)*2+half, lane2=lane.
    const int b = bh >> 4, h = bh & 15;
    const float inv0 = 1.0f / l0, inv1 = 1.0f / l1;
    const int m0r = b * SS + qt * 128 + warp * 16 + lr;
    const int mt = m0r >> 7;
    uint32_t* abase = (uint32_t*)g_af + (size_t)(mt * 16 + h) * 4096;
#pragma unroll
    for (int nf = 0; nf < 8; nf++) {
        const uint32_t w0 = pack_f16x2(o[nf][0] * inv0, o[nf][1] * inv0);
        const uint32_t w1 = pack_f16x2(o[nf][2] * inv1, o[nf][3] * inv1);
        const int widx = (((nf >> 1) * 8 + warp) * 32 + lane) * 4 + (nf & 1) * 2;
        abase[widx]     = w0;
        abase[widx + 1] = w1;
    }
}

// ---------------------------------------------------------------------------
extern "C" void kernel_launch(void* const* d_in, const int* in_sizes, int n_in,
                              void* d_out, int out_size)
{
    const float* x     = (const float*)d_in[0];
    const float* w_qkv = (const float*)d_in[1];
    const float* b_qkv = (const float*)d_in[2];
    const float* w_out = (const float*)d_in[3];
    const float* b_out = (const float*)d_in[4];
    float* out = (float*)d_out;

    (void)in_sizes; (void)n_in; (void)out_size;

    cudaFuncSetAttribute(f16_gemm<0>,
                         cudaFuncAttributeMaxDynamicSharedMemorySize, GEMM_SMEM);
    cudaFuncSetAttribute(f16_gemm<1>,
                         cudaFuncAttributeMaxDynamicSharedMemorySize, GEMM_SMEM);
    cudaFuncSetAttribute(fa_attn,
                         cudaFuncAttributeMaxDynamicSharedMemorySize, FA_SMEM);

    // 1) fragment-pack x, w_qkv, w_out (all fp16 m16n8k16 fragments)
    prep_xa<<<BS * 512 / 256, 256>>>(x);
    prep_w<0><<<512 * N_QKV / 256, 256>>>(w_qkv);
    prep_w<1><<<512 * EE / 256, 256>>>(w_out);
    // 2) QKV projection (single-pass fp16 HMMA) -> fp16 attention fragments
    {
        dim3 grid(N_QKV / 128, BS / 128);
        f16_gemm<0><<<grid, 256, GEMM_SMEM>>>(b_qkv, nullptr);
    }
    // 3) attention (fp16 QK + fp16 PV) -> out-proj fp16 A-fragments
    {
        dim3 grid(SS / 128, BB * HH);
        fa_attn<<<grid, 256, FA_SMEM>>>();
    }
    // 4) output projection (single-pass fp16 HMMA)
    {
        dim3 grid(EE / 128, BS / 128);
        f16_gemm<1><<<grid, 256, GEMM_SMEM>>>(b_out, out);
    }
}